// round 12
// baseline (speedup 1.0000x reference)
#include <cuda_runtime.h>
#include <cuda_fp16.h>
#include <cstdint>
#include <math.h>

#define Bz 4
#define Nn 2048
#define Dd 512
#define Hh 8
#define Cc 64
#define HC 512

// ---------------- device scratch ----------------
__device__ float  g_X [(size_t)Bz * Nn * HC];    // projected features [B,N,HC]
__device__ __half g_XTh[(size_t)Bz * HC * Nn];   // transposed fp16, i-pair permuted
__device__ __half g_EsH [(size_t)Bz * Hh * Nn];  // exp(s-4)  fp16 [b][h][n]
__device__ __half g_Es2H[(size_t)Bz * Hh * Nn];  // exp(.2s-4) fp16
__device__ float  g_EdT [(size_t)Bz * Hh * Nn];  // exp(d)   fp32
__device__ float  g_Ed2T[(size_t)Bz * Hh * Nn];  // exp(.2d) fp32
__device__ unsigned short g_adjH[(size_t)Bz * Nn * Nn]; // mask [b][j][i] 0xFFFF/0, diag folded

// ---------------- helpers ----------------
__device__ __forceinline__ uint32_t smem_u32(const void* p) {
    uint32_t a;
    asm("{ .reg .u64 t; cvta.to.shared.u64 t, %1; cvt.u32.u64 %0, t; }"
        : "=r"(a) : "l"(p));
    return a;
}
__device__ __forceinline__ uint32_t tf32u(uint32_t x) {
    uint32_t r;
    asm("cvt.rna.tf32.f32 %0, %1;" : "=r"(r) : "f"(__uint_as_float(x)));
    return r;
}
__device__ __forceinline__ uint2 lds64u(uint32_t a) {
    uint2 v;
    asm volatile("ld.shared.v2.u32 {%0,%1}, [%2];"
                 : "=r"(v.x), "=r"(v.y) : "r"(a));
    return v;
}
__device__ __forceinline__ uint32_t lds32u(uint32_t a) {
    uint32_t v;
    asm volatile("ld.shared.u32 %0, [%1];" : "=r"(v) : "r"(a));
    return v;
}
__device__ __forceinline__ void sts16(uint32_t a, uint16_t v) {
    asm volatile("st.shared.u16 [%0], %1;" :: "r"(a), "h"(v) : "memory");
}
__device__ __forceinline__ uint16_t f2h(float f) {
    __half h = __float2half_rn(f);
    return *(uint16_t*)&h;
}

#define CP_ASYNC16(dst, src) \
    asm volatile("cp.async.cg.shared.global [%0], [%1], 16;" \
                 :: "r"(dst), "l"(src) : "memory")
#define CP_COMMIT()  asm volatile("cp.async.commit_group;" ::: "memory")
#define CP_WAIT2()   asm volatile("cp.async.wait_group 2;" ::: "memory")

// tf32 mma (proj kernel)
__device__ __forceinline__ void mma8(float* d,
                                     uint32_t a0, uint32_t a1, uint32_t a2, uint32_t a3,
                                     uint32_t b0, uint32_t b1) {
    asm volatile(
        "mma.sync.aligned.m16n8k8.row.col.f32.tf32.tf32.f32 "
        "{%0,%1,%2,%3}, {%4,%5,%6,%7}, {%8,%9}, {%0,%1,%2,%3};"
        : "+f"(d[0]), "+f"(d[1]), "+f"(d[2]), "+f"(d[3])
        : "r"(a0), "r"(a1), "r"(a2), "r"(a3), "r"(b0), "r"(b1));
}
// fp16 mma (agg kernel)
__device__ __forceinline__ void mma16(float* d,
                                      uint32_t a0, uint32_t a1, uint32_t a2, uint32_t a3,
                                      uint32_t b0, uint32_t b1) {
    asm volatile(
        "mma.sync.aligned.m16n8k16.row.col.f32.f16.f16.f32 "
        "{%0,%1,%2,%3}, {%4,%5,%6,%7}, {%8,%9}, {%0,%1,%2,%3};"
        : "+f"(d[0]), "+f"(d[1]), "+f"(d[2]), "+f"(d[3])
        : "r"(a0), "r"(a1), "r"(a2), "r"(a3), "r"(b0), "r"(b1));
}
#define ONES_H2 0x3C003C00u

// ---------------- fast exp (FFMA-only) ----------------
__device__ __forceinline__ float fexp(float x) {
    const float LOG2E = 1.4426950408889634f;
    float t = x * LOG2E;
    float z = t + 12582912.0f;
    int   n = __float_as_int(z) - 0x4B400000;
    float r = z - 12582912.0f;
    float f = t - r;
    float u = f * 0.69314718056f;
    float p = 8.3333333e-3f;
    p = p * u + 4.1666667e-2f;
    p = p * u + 1.6666667e-1f;
    p = p * u + 0.5f;
    p = p * u + 1.0f;
    p = p * u + 1.0f;
    return p * __int_as_float((n + 127) << 23);
}

// ---------------------------------------------------------------------------
// Kernel 1: adjacency -> transposed fp16 AND-mask (diag folded)
// ---------------------------------------------------------------------------
__global__ __launch_bounds__(256) void pack_adjH(const int* __restrict__ adj)
{
    __shared__ unsigned short ts[32][36];
    const int b  = blockIdx.z;
    const int i0 = blockIdx.y * 32;
    const int j0 = blockIdx.x * 32;
    const int t  = threadIdx.x;
    const int r  = t >> 3;
    const int c4 = t & 7;

    int4 v = *(const int4*)(adj + ((size_t)b * Nn + i0 + r) * Nn + j0 + c4 * 4);
    const int ii = i0 + r;
    ts[r][c4 * 4 + 0] = (v.x != 0 || ii == j0 + c4 * 4 + 0) ? 0xFFFFu : 0u;
    ts[r][c4 * 4 + 1] = (v.y != 0 || ii == j0 + c4 * 4 + 1) ? 0xFFFFu : 0u;
    ts[r][c4 * 4 + 2] = (v.z != 0 || ii == j0 + c4 * 4 + 2) ? 0xFFFFu : 0u;
    ts[r][c4 * 4 + 3] = (v.w != 0 || ii == j0 + c4 * 4 + 3) ? 0xFFFFu : 0u;
    __syncthreads();

    const int jr  = t >> 3;
    const int ic4 = t & 7;
    uint32_t lo = (uint32_t)ts[ic4 * 4 + 0][jr] | ((uint32_t)ts[ic4 * 4 + 1][jr] << 16);
    uint32_t hi = (uint32_t)ts[ic4 * 4 + 2][jr] | ((uint32_t)ts[ic4 * 4 + 3][jr] << 16);
    *(uint2*)(g_adjH + ((size_t)b * Nn + j0 + jr) * Nn + i0 + ic4 * 4) =
        make_uint2(lo, hi);
}

// ---------------------------------------------------------------------------
// Kernel 2: projection GEMM (mma.sync tf32, cp.async 4-stage) + fused
// transposed fp16 epilogue (unchanged from R11).
// ---------------------------------------------------------------------------
#define PA_OFF 0u
#define PB_OFF 40960u
#define PROJ_SMEM 75776u

__global__ void __launch_bounds__(256, 2) gemm_proj_mma(
    const float* __restrict__ A, const float* __restrict__ Wm)
{
    extern __shared__ float sm[];
    const uint32_t sb = smem_u32(sm);

    const int t  = threadIdx.x;
    const int m0 = blockIdx.x * 128;
    const int n0 = blockIdx.y * 128;
    const int wid = t >> 5, lane = t & 31;
    const int wm = wid & 1, wn = wid >> 1;
    const int g = lane >> 2, tg = lane & 3;

    float acc[4][4][4];
    #pragma unroll
    for (int i = 0; i < 4; i++)
        #pragma unroll
        for (int j = 0; j < 4; j++)
            #pragma unroll
            for (int r = 0; r < 4; r++) acc[i][j][r] = 0.f;

    const float* asrc[2]; uint32_t adst[2];
    const float* bsrc[2]; uint32_t bdst[2];
    #pragma unroll
    for (int u = 0; u < 2; u++) {
        int gid = u * 256 + t;
        int ar = gid >> 2, ag = gid & 3;
        asrc[u] = A + (size_t)(m0 + ar) * Dd + ag * 4;
        adst[u] = sb + PA_OFF + (uint32_t)(ar * 80 + ag * 16);
        int br = gid >> 5, bg = gid & 31;
        bsrc[u] = Wm + (size_t)br * HC + n0 + bg * 4;
        bdst[u] = sb + PB_OFF + (uint32_t)(br * 544 + bg * 16);
    }

    #pragma unroll
    for (int s = 0; s < 3; s++) {
        #pragma unroll
        for (int u = 0; u < 2; u++) {
            CP_ASYNC16(adst[u] + s * 10240u, asrc[u] + s * 16);
            CP_ASYNC16(bdst[u] + s * 8704u,  bsrc[u] + (size_t)(s * 16) * HC);
        }
        CP_COMMIT();
    }

    for (int kc = 0; kc < 32; ++kc) {
        const int buf = kc & 3;
        CP_WAIT2();
        __syncthreads();
        if (kc < 29) {
            const int s = (kc + 3) & 3, k0 = (kc + 3) * 16;
            #pragma unroll
            for (int u = 0; u < 2; u++) {
                CP_ASYNC16(adst[u] + s * 10240u, asrc[u] + k0);
                CP_ASYNC16(bdst[u] + s * 8704u,  bsrc[u] + (size_t)k0 * HC);
            }
            CP_COMMIT();
        } else {
            CP_COMMIT();
        }

        const uint32_t Ab = sb + PA_OFF + buf * 10240u + (uint32_t)(wm * 64) * 80u;
        const uint32_t Bb = sb + PB_OFF + buf * 8704u + (uint32_t)(wn * 32) * 4u;

        #pragma unroll
        for (int ks = 0; ks < 2; ks++) {
            uint32_t a[4][4];
            #pragma unroll
            for (int mt = 0; mt < 4; mt++) {
                const uint32_t base = Ab + (uint32_t)((mt * 16 + g) * 80 + (ks * 8 + tg) * 4);
                a[mt][0] = tf32u(lds32u(base));
                a[mt][1] = tf32u(lds32u(base + 640u));
                a[mt][2] = tf32u(lds32u(base + 16u));
                a[mt][3] = tf32u(lds32u(base + 656u));
            }
            uint2 bf[4];
            #pragma unroll
            for (int nt = 0; nt < 4; nt++) {
                const uint32_t base = Bb + (uint32_t)((ks * 8 + tg) * 544 + (nt * 8 + g) * 4);
                bf[nt].x = tf32u(lds32u(base));
                bf[nt].y = tf32u(lds32u(base + 2176u));
            }
            #pragma unroll
            for (int mt = 0; mt < 4; mt++)
                #pragma unroll
                for (int nt = 0; nt < 4; nt++)
                    mma8(acc[mt][nt], a[mt][0], a[mt][1], a[mt][2], a[mt][3],
                         bf[nt].x, bf[nt].y);
        }
    }

    #pragma unroll
    for (int mt = 0; mt < 4; mt++) {
        const int m = m0 + wm * 64 + mt * 16 + g;
        #pragma unroll
        for (int nt = 0; nt < 4; nt++) {
            const int n = n0 + wn * 32 + nt * 8 + tg * 2;
            *(float2*)(g_X + (size_t)m * HC + n)       = make_float2(acc[mt][nt][0], acc[mt][nt][1]);
            *(float2*)(g_X + (size_t)(m + 8) * HC + n) = make_float2(acc[mt][nt][2], acc[mt][nt][3]);
        }
    }

    __syncthreads();
    #pragma unroll
    for (int mt = 0; mt < 4; mt++) {
        const int ml = wm * 64 + mt * 16 + g;
        #pragma unroll
        for (int nt = 0; nt < 4; nt++) {
            const int hcl = wn * 32 + nt * 8 + tg * 2;
            sts16(sb + (uint32_t)(hcl * 272 + ml * 2),             f2h(acc[mt][nt][0]));
            sts16(sb + (uint32_t)((hcl + 1) * 272 + ml * 2),       f2h(acc[mt][nt][1]));
            sts16(sb + (uint32_t)(hcl * 272 + (ml + 8) * 2),       f2h(acc[mt][nt][2]));
            sts16(sb + (uint32_t)((hcl + 1) * 272 + (ml + 8) * 2), f2h(acc[mt][nt][3]));
        }
    }
    __syncthreads();

    const int bb = m0 >> 11, mloc = m0 & 2047;
    #pragma unroll 1
    for (int pass = 0; pass < 16; pass++) {
        const int row = pass * 8 + (t >> 5);
        const int ln  = t & 31;
        __half* orow = g_XTh + ((size_t)bb * HC + n0 + row) * Nn + mloc;
        #pragma unroll
        for (int k = 0; k < 2; k++) {
            const int wi = ln + k * 32;
            const int w16 = wi & 15, grp = wi >> 4;
            const int p16 = (w16 & 8) | ((w16 & 3) << 1) | ((w16 >> 2) & 1);
            uint32_t v = lds32u(sb + (uint32_t)(row * 272 + wi * 4));
            *(uint32_t*)(orow + (grp * 16 + p16) * 2) = v;
        }
    }
}

// ---------------------------------------------------------------------------
// Kernel 3: attention scores (unchanged R11)
// ---------------------------------------------------------------------------
__global__ __launch_bounds__(256) void att_prep(
    const float* __restrict__ att_src, const float* __restrict__ att_dst)
{
    __shared__ float sa[HC], sdv[HC];
    const int t = threadIdx.x;
    if (t < 128)       ((float4*)sa)[t]        = ((const float4*)att_src)[t];
    else               ((float4*)sdv)[t - 128] = ((const float4*)att_dst)[t - 128];
    __syncthreads();

    const int w = t >> 5, l = t & 31;
    const int bn = blockIdx.x * 8 + w;
    const int b = bn >> 11, n = bn & 2047;
    const float* xp = g_X + (size_t)bn * HC;

    float sp[4], dp[4];
    #pragma unroll
    for (int p = 0; p < 4; p++) {
        const int c = p * 128 + l * 4;
        float4 xv = *(const float4*)(xp + c);
        float4 av = *(const float4*)(sa + c);
        float4 dv = *(const float4*)(sdv + c);
        sp[p] = xv.x * av.x + xv.y * av.y + xv.z * av.z + xv.w * av.w;
        dp[p] = xv.x * dv.x + xv.y * dv.y + xv.z * dv.z + xv.w * dv.w;
    }
    #pragma unroll
    for (int o = 1; o < 16; o <<= 1) {
        #pragma unroll
        for (int p = 0; p < 4; p++) {
            sp[p] += __shfl_xor_sync(0xffffffffu, sp[p], o);
            dp[p] += __shfl_xor_sync(0xffffffffu, dp[p], o);
        }
    }
    const int hi = l >> 4, q = l & 15;
    const int p = q >> 2, v = q & 3;
    const int h = p * 2 + hi;
    const float s = sp[p], d = dp[p];
    const size_t o = ((size_t)b * Hh + h) * Nn + n;
    if      (v == 0) g_EsH [o] = __float2half_rn(fexp(s - 4.0f));
    else if (v == 1) g_Es2H[o] = __float2half_rn(fexp(0.2f * s - 4.0f));
    else if (v == 2) g_EdT [o] = fexp(d);
    else             g_Ed2T[o] = fexp(0.2f * d);
}

// ---------------------------------------------------------------------------
// Kernel 4: fused masked-softmax aggregation, fp16 MMA.
// ONE head per block (grid 512) -> acc halves -> 3 blocks/SM (24 warps):
// +50% occupancy to hide LDS->MMA latency.
// ---------------------------------------------------------------------------
#define XT_OFFB  0u        // 4 stages x 4096B (64 c-rows x 64B)
#define AH_OFFB  16384u    // 4 stages x 8192B (128 j-rows x 64B)
#define ES_OFFB  49152u    // 4 stages x 128B ([var2][32 halfs])
#define AGG_SMEM 49664u

__global__ void __launch_bounds__(256, 3) gat_agg_mma(
    const float* __restrict__ bias, float* __restrict__ out)
{
    extern __shared__ float sm[];
    const uint32_t sb = smem_u32(sm);

    const int t  = threadIdx.x;
    const int b  = blockIdx.z;
    const int h0 = blockIdx.y;           // one head per block
    const int j0 = blockIdx.x * 128;

    const int wid = t >> 5, lane = t & 31;
    const int ctw = wid;                 // 8 warps x 16 j-rows
    const int g = lane >> 2, tg = lane & 3;

    const size_t bn0 = (size_t)b * Nn;
    const size_t edb = ((size_t)b * Hh + h0) * Nn + j0;

    // 2 fragment rows this thread owns
    int rows[2]; __half2 edh[2], ed2h[2];
    #pragma unroll
    for (int r = 0; r < 2; r++) {
        rows[r] = ctw * 16 + r * 8 + g;
        edh[r]  = __half2half2(__float2half_rn(g_EdT [edb + rows[r]]));
        ed2h[r] = __half2half2(__float2half_rn(g_Ed2T[edb + rows[r]]));
    }

    float acc[8][4];
    #pragma unroll
    for (int n = 0; n < 8; n++)
        #pragma unroll
        for (int r = 0; r < 4; r++) acc[n][r] = 0.f;
    float accl[4];
    #pragma unroll
    for (int r = 0; r < 4; r++) accl[r] = 0.f;

    // cp.async bases
    // XT: 64 c-rows x 64B = 4KB/stage; 256 threads x 16B
    const __half* xsrc; uint32_t xdst;
    {
        int row = t >> 2, q = t & 3;
        xsrc = g_XTh + ((size_t)b * HC + (size_t)h0 * Cc + row) * Nn + q * 8;
        xdst = sb + XT_OFFB + (uint32_t)(row * 64 + ((q ^ ((row >> 1) & 3)) << 4));
    }
    // adj: 128 j-rows x 64B = 8KB/stage; 512 granules
    const unsigned short* asrc[2]; uint32_t adst[2];
    #pragma unroll
    for (int u = 0; u < 2; u++) {
        int gid = u * 256 + t;
        int row = gid >> 2, q = gid & 3;
        asrc[u] = g_adjH + (bn0 + j0 + row) * Nn + q * 8;
        adst[u] = sb + AH_OFFB + (uint32_t)(row * 64 + ((q ^ ((row >> 1) & 3)) << 4));
    }
    // ES: 2 vars x 32 halfs = 128B/stage; 8 threads x 16B
    const __half* essrc = nullptr; uint32_t esdst = 0;
    if (t < 8) {
        int var = t >> 2, gi = t & 3;
        const __half* tbl = var ? g_Es2H : g_EsH;
        essrc = tbl + ((size_t)b * Hh + h0) * Nn + gi * 8;
        esdst = sb + ES_OFFB + (uint32_t)(var * 64 + gi * 16);
    }

    // prologue: stages 0..2
    #pragma unroll
    for (int s = 0; s < 3; s++) {
        CP_ASYNC16(xdst + s * 4096u, xsrc + s * 32);
        #pragma unroll
        for (int u = 0; u < 2; u++)
            CP_ASYNC16(adst[u] + s * 8192u, asrc[u] + s * 32);
        if (t < 8) CP_ASYNC16(esdst + s * 128u, essrc + s * 32);
        CP_COMMIT();
    }

    for (int ch = 0; ch < 64; ++ch) {
        const int s4 = ch & 3;
        CP_WAIT2();
        __syncthreads();

        if (ch <= 60) {
            const int s = ch + 3, sw = s & 3;
            CP_ASYNC16(xdst + (uint32_t)sw * 4096u, xsrc + s * 32);
            #pragma unroll
            for (int u = 0; u < 2; u++)
                CP_ASYNC16(adst[u] + (uint32_t)sw * 8192u, asrc[u] + s * 32);
            if (t < 8) CP_ASYNC16(esdst + (uint32_t)sw * 128u, essrc + s * 32);
            CP_COMMIT();
        } else {
            CP_COMMIT();
        }

        const uint32_t esb0 = sb + ES_OFFB + (uint32_t)(s4 * 128);
        const uint32_t esb2 = esb0 + 64u;
        const uint32_t xtb  = sb + XT_OFFB + (uint32_t)(s4 * 4096);
        const uint32_t ahb  = sb + AH_OFFB + (uint32_t)(s4 * 8192);

        #pragma unroll
        for (int ks = 0; ks < 2; ks++) {
            const uint32_t eo = (uint32_t)(ks * 32 + tg * 4);
            uint32_t uesA = lds32u(esb0 + eo);
            uint32_t uesB = lds32u(esb0 + eo + 16u);
            uint32_t ue2A = lds32u(esb2 + eo);
            uint32_t ue2B = lds32u(esb2 + eo + 16u);
            const __half2 esA = *(__half2*)&uesA, esB = *(__half2*)&uesB;
            const __half2 e2A = *(__half2*)&ue2A, e2B = *(__half2*)&ue2B;

            uint32_t aT[2], bT[2];
            #pragma unroll
            for (int r = 0; r < 2; r++) {
                const uint32_t rb  = ahb + (uint32_t)(rows[r] * 64);
                const uint32_t sxr = (uint32_t)(((rows[r] >> 1) & 3) << 2);
                uint32_t mA = lds32u(rb + ((((uint32_t)(ks * 8 + tg)) ^ sxr) << 2));
                uint32_t mB = lds32u(rb + ((((uint32_t)(ks * 8 + tg + 4)) ^ sxr) << 2));
                __half2 va = __hmax2(__hmul2(esA, edh[r]), __hmul2(e2A, ed2h[r]));
                __half2 vb = __hmax2(__hmul2(esB, edh[r]), __hmul2(e2B, ed2h[r]));
                aT[r] = (*(uint32_t*)&va) & mA;
                bT[r] = (*(uint32_t*)&vb) & mB;
            }

            #pragma unroll
            for (int nt = 0; nt < 8; nt++) {
                const int r = nt * 8 + g;
                const uint32_t g16 = (uint32_t)(ks * 2 + (tg >> 1)) ^ (uint32_t)((r >> 1) & 3);
                uint2 u = lds64u(xtb + (uint32_t)(r * 64) + g16 * 16u + (uint32_t)((tg & 1) * 8));
                mma16(acc[nt], aT[0], aT[1], bT[0], bT[1], u.x, u.y);
            }
            mma16(accl, aT[0], aT[1], bT[0], bT[1], ONES_H2, ONES_H2);
        }
    }

    // ---- epilogue: normalize, +bias, ELU, store
    const float* bp = bias + (size_t)h0 * Cc;
    const int r0 = ctw * 16 + g;
    const int r1 = r0 + 8;
    const float inv0 = 1.f / accl[0];
    const float inv1 = 1.f / accl[2];
    float* o0 = out + (bn0 + j0 + r0) * HC + (size_t)h0 * Cc;
    float* o1 = out + (bn0 + j0 + r1) * HC + (size_t)h0 * Cc;
    #pragma unroll
    for (int nt = 0; nt < 8; nt++) {
        const int c = nt * 8 + tg * 2;
        const float b0v = bp[c], b1v = bp[c + 1];
        float w0 = acc[nt][0] * inv0 + b0v;
        float w1 = acc[nt][1] * inv0 + b1v;
        float w2 = acc[nt][2] * inv1 + b0v;
        float w3 = acc[nt][3] * inv1 + b1v;
        w0 = w0 > 0.f ? w0 : (fexp(w0) - 1.f);
        w1 = w1 > 0.f ? w1 : (fexp(w1) - 1.f);
        w2 = w2 > 0.f ? w2 : (fexp(w2) - 1.f);
        w3 = w3 > 0.f ? w3 : (fexp(w3) - 1.f);
        *(float2*)(o0 + c) = make_float2(w0, w1);
        *(float2*)(o1 + c) = make_float2(w2, w3);
    }
}

// ---------------------------------------------------------------------------
extern "C" void kernel_launch(void* const* d_in, const int* in_sizes, int n_in,
                              void* d_out, int out_size)
{
    const float* feats   = (const float*)d_in[0];
    const int*   adj     = (const int*)  d_in[1];
    const float* W       = (const float*)d_in[2];
    const float* att_src = (const float*)d_in[3];
    const float* att_dst = (const float*)d_in[4];
    const float* bias    = (const float*)d_in[5];
    float*       out     = (float*)d_out;
    (void)in_sizes; (void)n_in; (void)out_size;

    static bool attr_set = false;
    if (!attr_set) {
        cudaFuncSetAttribute(gat_agg_mma,
                             cudaFuncAttributeMaxDynamicSharedMemorySize, AGG_SMEM);
        cudaFuncSetAttribute(gemm_proj_mma,
                             cudaFuncAttributeMaxDynamicSharedMemorySize, PROJ_SMEM);
        attr_set = true;
    }

    pack_adjH<<<dim3(Nn / 32, Nn / 32, Bz), 256>>>(adj);
    gemm_proj_mma<<<dim3((Bz * Nn) / 128, HC / 128), 256, PROJ_SMEM>>>(feats, W);
    att_prep<<<(Bz * Nn) / 8, 256>>>(att_src, att_dst);
    gat_agg_mma<<<dim3(Nn / 128, Hh, Bz), 256, AGG_SMEM>>>(bias, out);
}

// round 14
// speedup vs baseline: 1.2798x; 1.2798x over previous
#include <cuda_runtime.h>
#include <cuda_fp16.h>
#include <cstdint>
#include <math.h>

#define Bz 4
#define Nn 2048
#define Dd 512
#define Hh 8
#define Cc 64
#define HC 512

// ---------------- device scratch ----------------
__device__ float  g_X [(size_t)Bz * Nn * HC];    // projected features [B,N,HC]
__device__ __half g_XTh[(size_t)Bz * HC * Nn];   // transposed fp16, i-pair permuted
__device__ __half g_EsH [(size_t)Bz * Hh * Nn];  // exp(s-4)  fp16 [b][h][n]
__device__ __half g_Es2H[(size_t)Bz * Hh * Nn];  // exp(.2s-4) fp16
__device__ float  g_EdT [(size_t)Bz * Hh * Nn];  // exp(d)   fp32
__device__ float  g_Ed2T[(size_t)Bz * Hh * Nn];  // exp(.2d) fp32
__device__ unsigned short g_adjH[(size_t)Bz * Nn * Nn]; // mask [b][j][i] 0xFFFF/0, diag folded

// ---------------- helpers ----------------
__device__ __forceinline__ uint32_t smem_u32(const void* p) {
    uint32_t a;
    asm("{ .reg .u64 t; cvta.to.shared.u64 t, %1; cvt.u32.u64 %0, t; }"
        : "=r"(a) : "l"(p));
    return a;
}
__device__ __forceinline__ uint32_t tf32u(uint32_t x) {
    uint32_t r;
    asm("cvt.rna.tf32.f32 %0, %1;" : "=r"(r) : "f"(__uint_as_float(x)));
    return r;
}
__device__ __forceinline__ uint2 lds64u(uint32_t a) {
    uint2 v;
    asm volatile("ld.shared.v2.u32 {%0,%1}, [%2];"
                 : "=r"(v.x), "=r"(v.y) : "r"(a));
    return v;
}
__device__ __forceinline__ uint32_t lds32u(uint32_t a) {
    uint32_t v;
    asm volatile("ld.shared.u32 %0, [%1];" : "=r"(v) : "r"(a));
    return v;
}
__device__ __forceinline__ void sts16(uint32_t a, uint16_t v) {
    asm volatile("st.shared.u16 [%0], %1;" :: "r"(a), "h"(v) : "memory");
}
__device__ __forceinline__ uint16_t f2h(float f) {
    __half h = __float2half_rn(f);
    return *(uint16_t*)&h;
}

#define CP_ASYNC16(dst, src) \
    asm volatile("cp.async.cg.shared.global [%0], [%1], 16;" \
                 :: "r"(dst), "l"(src) : "memory")
#define CP_COMMIT()  asm volatile("cp.async.commit_group;" ::: "memory")
#define CP_WAIT1()   asm volatile("cp.async.wait_group 1;" ::: "memory")
#define CP_WAIT2()   asm volatile("cp.async.wait_group 2;" ::: "memory")

// tf32 mma (proj kernel)
__device__ __forceinline__ void mma8(float* d,
                                     uint32_t a0, uint32_t a1, uint32_t a2, uint32_t a3,
                                     uint32_t b0, uint32_t b1) {
    asm volatile(
        "mma.sync.aligned.m16n8k8.row.col.f32.tf32.tf32.f32 "
        "{%0,%1,%2,%3}, {%4,%5,%6,%7}, {%8,%9}, {%0,%1,%2,%3};"
        : "+f"(d[0]), "+f"(d[1]), "+f"(d[2]), "+f"(d[3])
        : "r"(a0), "r"(a1), "r"(a2), "r"(a3), "r"(b0), "r"(b1));
}
// fp16 mma (agg kernel)
__device__ __forceinline__ void mma16(float* d,
                                      uint32_t a0, uint32_t a1, uint32_t a2, uint32_t a3,
                                      uint32_t b0, uint32_t b1) {
    asm volatile(
        "mma.sync.aligned.m16n8k16.row.col.f32.f16.f16.f32 "
        "{%0,%1,%2,%3}, {%4,%5,%6,%7}, {%8,%9}, {%0,%1,%2,%3};"
        : "+f"(d[0]), "+f"(d[1]), "+f"(d[2]), "+f"(d[3])
        : "r"(a0), "r"(a1), "r"(a2), "r"(a3), "r"(b0), "r"(b1));
}
#define ONES_H2 0x3C003C00u

// ---------------- fast exp (FFMA-only) ----------------
__device__ __forceinline__ float fexp(float x) {
    const float LOG2E = 1.4426950408889634f;
    float t = x * LOG2E;
    float z = t + 12582912.0f;
    int   n = __float_as_int(z) - 0x4B400000;
    float r = z - 12582912.0f;
    float f = t - r;
    float u = f * 0.69314718056f;
    float p = 8.3333333e-3f;
    p = p * u + 4.1666667e-2f;
    p = p * u + 1.6666667e-1f;
    p = p * u + 0.5f;
    p = p * u + 1.0f;
    p = p * u + 1.0f;
    return p * __int_as_float((n + 127) << 23);
}

// ---------------------------------------------------------------------------
// Kernel 1: adjacency -> transposed fp16 AND-mask (diag folded)
// ---------------------------------------------------------------------------
__global__ __launch_bounds__(256) void pack_adjH(const int* __restrict__ adj)
{
    __shared__ unsigned short ts[32][36];
    const int b  = blockIdx.z;
    const int i0 = blockIdx.y * 32;
    const int j0 = blockIdx.x * 32;
    const int t  = threadIdx.x;
    const int r  = t >> 3;
    const int c4 = t & 7;

    int4 v = *(const int4*)(adj + ((size_t)b * Nn + i0 + r) * Nn + j0 + c4 * 4);
    const int ii = i0 + r;
    ts[r][c4 * 4 + 0] = (v.x != 0 || ii == j0 + c4 * 4 + 0) ? 0xFFFFu : 0u;
    ts[r][c4 * 4 + 1] = (v.y != 0 || ii == j0 + c4 * 4 + 1) ? 0xFFFFu : 0u;
    ts[r][c4 * 4 + 2] = (v.z != 0 || ii == j0 + c4 * 4 + 2) ? 0xFFFFu : 0u;
    ts[r][c4 * 4 + 3] = (v.w != 0 || ii == j0 + c4 * 4 + 3) ? 0xFFFFu : 0u;
    __syncthreads();

    const int jr  = t >> 3;
    const int ic4 = t & 7;
    uint32_t lo = (uint32_t)ts[ic4 * 4 + 0][jr] | ((uint32_t)ts[ic4 * 4 + 1][jr] << 16);
    uint32_t hi = (uint32_t)ts[ic4 * 4 + 2][jr] | ((uint32_t)ts[ic4 * 4 + 3][jr] << 16);
    *(uint2*)(g_adjH + ((size_t)b * Nn + j0 + jr) * Nn + i0 + ic4 * 4) =
        make_uint2(lo, hi);
}

// ---------------------------------------------------------------------------
// Kernel 2: projection GEMM (mma.sync tf32, cp.async 4-stage) + fused
// transposed fp16 epilogue (unchanged).
// ---------------------------------------------------------------------------
#define PA_OFF 0u
#define PB_OFF 40960u
#define PROJ_SMEM 75776u

__global__ void __launch_bounds__(256, 2) gemm_proj_mma(
    const float* __restrict__ A, const float* __restrict__ Wm)
{
    extern __shared__ float sm[];
    const uint32_t sb = smem_u32(sm);

    const int t  = threadIdx.x;
    const int m0 = blockIdx.x * 128;
    const int n0 = blockIdx.y * 128;
    const int wid = t >> 5, lane = t & 31;
    const int wm = wid & 1, wn = wid >> 1;
    const int g = lane >> 2, tg = lane & 3;

    float acc[4][4][4];
    #pragma unroll
    for (int i = 0; i < 4; i++)
        #pragma unroll
        for (int j = 0; j < 4; j++)
            #pragma unroll
            for (int r = 0; r < 4; r++) acc[i][j][r] = 0.f;

    const float* asrc[2]; uint32_t adst[2];
    const float* bsrc[2]; uint32_t bdst[2];
    #pragma unroll
    for (int u = 0; u < 2; u++) {
        int gid = u * 256 + t;
        int ar = gid >> 2, ag = gid & 3;
        asrc[u] = A + (size_t)(m0 + ar) * Dd + ag * 4;
        adst[u] = sb + PA_OFF + (uint32_t)(ar * 80 + ag * 16);
        int br = gid >> 5, bg = gid & 31;
        bsrc[u] = Wm + (size_t)br * HC + n0 + bg * 4;
        bdst[u] = sb + PB_OFF + (uint32_t)(br * 544 + bg * 16);
    }

    #pragma unroll
    for (int s = 0; s < 3; s++) {
        #pragma unroll
        for (int u = 0; u < 2; u++) {
            CP_ASYNC16(adst[u] + s * 10240u, asrc[u] + s * 16);
            CP_ASYNC16(bdst[u] + s * 8704u,  bsrc[u] + (size_t)(s * 16) * HC);
        }
        CP_COMMIT();
    }

    for (int kc = 0; kc < 32; ++kc) {
        const int buf = kc & 3;
        CP_WAIT2();
        __syncthreads();
        if (kc < 29) {
            const int s = (kc + 3) & 3, k0 = (kc + 3) * 16;
            #pragma unroll
            for (int u = 0; u < 2; u++) {
                CP_ASYNC16(adst[u] + s * 10240u, asrc[u] + k0);
                CP_ASYNC16(bdst[u] + s * 8704u,  bsrc[u] + (size_t)k0 * HC);
            }
            CP_COMMIT();
        } else {
            CP_COMMIT();
        }

        const uint32_t Ab = sb + PA_OFF + buf * 10240u + (uint32_t)(wm * 64) * 80u;
        const uint32_t Bb = sb + PB_OFF + buf * 8704u + (uint32_t)(wn * 32) * 4u;

        #pragma unroll
        for (int ks = 0; ks < 2; ks++) {
            uint32_t a[4][4];
            #pragma unroll
            for (int mt = 0; mt < 4; mt++) {
                const uint32_t base = Ab + (uint32_t)((mt * 16 + g) * 80 + (ks * 8 + tg) * 4);
                a[mt][0] = tf32u(lds32u(base));
                a[mt][1] = tf32u(lds32u(base + 640u));
                a[mt][2] = tf32u(lds32u(base + 16u));
                a[mt][3] = tf32u(lds32u(base + 656u));
            }
            uint2 bf[4];
            #pragma unroll
            for (int nt = 0; nt < 4; nt++) {
                const uint32_t base = Bb + (uint32_t)((ks * 8 + tg) * 544 + (nt * 8 + g) * 4);
                bf[nt].x = tf32u(lds32u(base));
                bf[nt].y = tf32u(lds32u(base + 2176u));
            }
            #pragma unroll
            for (int mt = 0; mt < 4; mt++)
                #pragma unroll
                for (int nt = 0; nt < 4; nt++)
                    mma8(acc[mt][nt], a[mt][0], a[mt][1], a[mt][2], a[mt][3],
                         bf[nt].x, bf[nt].y);
        }
    }

    #pragma unroll
    for (int mt = 0; mt < 4; mt++) {
        const int m = m0 + wm * 64 + mt * 16 + g;
        #pragma unroll
        for (int nt = 0; nt < 4; nt++) {
            const int n = n0 + wn * 32 + nt * 8 + tg * 2;
            *(float2*)(g_X + (size_t)m * HC + n)       = make_float2(acc[mt][nt][0], acc[mt][nt][1]);
            *(float2*)(g_X + (size_t)(m + 8) * HC + n) = make_float2(acc[mt][nt][2], acc[mt][nt][3]);
        }
    }

    __syncthreads();
    #pragma unroll
    for (int mt = 0; mt < 4; mt++) {
        const int ml = wm * 64 + mt * 16 + g;
        #pragma unroll
        for (int nt = 0; nt < 4; nt++) {
            const int hcl = wn * 32 + nt * 8 + tg * 2;
            sts16(sb + (uint32_t)(hcl * 272 + ml * 2),             f2h(acc[mt][nt][0]));
            sts16(sb + (uint32_t)((hcl + 1) * 272 + ml * 2),       f2h(acc[mt][nt][1]));
            sts16(sb + (uint32_t)(hcl * 272 + (ml + 8) * 2),       f2h(acc[mt][nt][2]));
            sts16(sb + (uint32_t)((hcl + 1) * 272 + (ml + 8) * 2), f2h(acc[mt][nt][3]));
        }
    }
    __syncthreads();

    const int bb = m0 >> 11, mloc = m0 & 2047;
    #pragma unroll 1
    for (int pass = 0; pass < 16; pass++) {
        const int row = pass * 8 + (t >> 5);
        const int ln  = t & 31;
        __half* orow = g_XTh + ((size_t)bb * HC + n0 + row) * Nn + mloc;
        #pragma unroll
        for (int k = 0; k < 2; k++) {
            const int wi = ln + k * 32;
            const int w16 = wi & 15, grp = wi >> 4;
            const int p16 = (w16 & 8) | ((w16 & 3) << 1) | ((w16 >> 2) & 1);
            uint32_t v = lds32u(sb + (uint32_t)(row * 272 + wi * 4));
            *(uint32_t*)(orow + (grp * 16 + p16) * 2) = v;
        }
    }
}

// ---------------------------------------------------------------------------
// Kernel 3: attention scores (unchanged)
// ---------------------------------------------------------------------------
__global__ __launch_bounds__(256) void att_prep(
    const float* __restrict__ att_src, const float* __restrict__ att_dst)
{
    __shared__ float sa[HC], sdv[HC];
    const int t = threadIdx.x;
    if (t < 128)       ((float4*)sa)[t]        = ((const float4*)att_src)[t];
    else               ((float4*)sdv)[t - 128] = ((const float4*)att_dst)[t - 128];
    __syncthreads();

    const int w = t >> 5, l = t & 31;
    const int bn = blockIdx.x * 8 + w;
    const int b = bn >> 11, n = bn & 2047;
    const float* xp = g_X + (size_t)bn * HC;

    float sp[4], dp[4];
    #pragma unroll
    for (int p = 0; p < 4; p++) {
        const int c = p * 128 + l * 4;
        float4 xv = *(const float4*)(xp + c);
        float4 av = *(const float4*)(sa + c);
        float4 dv = *(const float4*)(sdv + c);
        sp[p] = xv.x * av.x + xv.y * av.y + xv.z * av.z + xv.w * av.w;
        dp[p] = xv.x * dv.x + xv.y * dv.y + xv.z * dv.z + xv.w * dv.w;
    }
    #pragma unroll
    for (int o = 1; o < 16; o <<= 1) {
        #pragma unroll
        for (int p = 0; p < 4; p++) {
            sp[p] += __shfl_xor_sync(0xffffffffu, sp[p], o);
            dp[p] += __shfl_xor_sync(0xffffffffu, dp[p], o);
        }
    }
    const int hi = l >> 4, q = l & 15;
    const int p = q >> 2, v = q & 3;
    const int h = p * 2 + hi;
    const float s = sp[p], d = dp[p];
    const size_t o = ((size_t)b * Hh + h) * Nn + n;
    if      (v == 0) g_EsH [o] = __float2half_rn(fexp(s - 4.0f));
    else if (v == 1) g_Es2H[o] = __float2half_rn(fexp(0.2f * s - 4.0f));
    else if (v == 2) g_EdT [o] = fexp(d);
    else             g_Ed2T[o] = fexp(0.2f * d);
}

// ---------------------------------------------------------------------------
// Kernel 4: fused masked-softmax aggregation — R11 structure (2 heads/block)
// with 64-i pipeline stages (2x 32-i subs) and 3-stage cp.async ring.
// ES producer layout now EXACTLY matches consumer:
//   slot(sub, var, head) at sub*512 + var*256 + head*128 (64B used per slot).
// ---------------------------------------------------------------------------
#define XT_OFFB  0u        // 3 stages x 16384B (2 subs x 128 rows x 64B)
#define AH_OFFB  49152u    // 3 stages x 16384B
#define ES_OFFB  98304u    // 3 stages x 1024B (sub*512 + var*256 + head*128)
#define AGG_SMEM 101376u

__global__ void __launch_bounds__(256, 2) gat_agg_mma(
    const float* __restrict__ bias, float* __restrict__ out)
{
    extern __shared__ float sm[];
    const uint32_t sb = smem_u32(sm);

    const int t  = threadIdx.x;
    const int b  = blockIdx.z;
    const int h0 = blockIdx.y * 2;
    const int j0 = blockIdx.x * 128;

    const int wid = t >> 5, lane = t & 31;
    const int chead = wid >> 2, ctw = wid & 3;
    const int g = lane >> 2, tg = lane & 3;

    const size_t bn0 = (size_t)b * Nn;
    const size_t edb = ((size_t)b * Hh + h0 + chead) * Nn + j0;

    int rows[4]; __half2 edh[4], ed2h[4];
    #pragma unroll
    for (int r = 0; r < 4; r++) {
        rows[r] = ctw * 32 + (r >> 1) * 16 + (r & 1) * 8 + g;
        edh[r]  = __half2half2(__float2half_rn(g_EdT [edb + rows[r]]));
        ed2h[r] = __half2half2(__float2half_rn(g_Ed2T[edb + rows[r]]));
    }

    float acc[2][8][4];
    #pragma unroll
    for (int m = 0; m < 2; m++)
        #pragma unroll
        for (int n = 0; n < 8; n++)
            #pragma unroll
            for (int r = 0; r < 4; r++) acc[m][n][r] = 0.f;
    float accl[2][4];
    #pragma unroll
    for (int m = 0; m < 2; m++)
        #pragma unroll
        for (int r = 0; r < 4; r++) accl[m][r] = 0.f;

    // cp.async bases (R11 mapping; per 64-i stage each thread moves 2 subs)
    const __half* xsrc[2]; uint32_t xdst[2];
    const unsigned short* asrc[2]; uint32_t adst[2];
    #pragma unroll
    for (int u = 0; u < 2; u++) {
        int gid = u * 256 + t;
        int row = gid >> 2, q = gid & 3;
        int hh = row >> 6, c = row & 63;
        xsrc[u] = g_XTh + ((size_t)b * HC + (size_t)(h0 + hh) * Cc + c) * Nn + q * 8;
        xdst[u] = sb + XT_OFFB + (uint32_t)(row * 64 + ((q ^ ((row >> 1) & 3)) << 4));
        asrc[u] = g_adjH + (bn0 + j0 + row) * Nn + q * 8;
        adst[u] = sb + AH_OFFB + (uint32_t)(row * 64 + ((q ^ ((row >> 1) & 3)) << 4));
    }
    const __half* essrc = nullptr; uint32_t esdst = 0;
    if (t < 32) {
        int sub = t >> 4, tt = t & 15;
        int seg = tt >> 2, gi = tt & 3;
        int var = seg >> 1, hh = seg & 1;
        const __half* tbl = var ? g_Es2H : g_EsH;
        essrc = tbl + ((size_t)b * Hh + h0 + hh) * Nn + sub * 32 + gi * 8;
        // FIXED: match consumer layout sub*512 + var*256 + head*128
        esdst = sb + ES_OFFB + (uint32_t)(sub * 512 + var * 256 + hh * 128 + gi * 16);
    }

    // prologue: stages 0..1 (each stage = 64 i = 2 subs)
    #pragma unroll
    for (int s = 0; s < 2; s++) {
        #pragma unroll
        for (int d = 0; d < 2; d++) {
            const int io = s * 64 + d * 32;   // element offset (halfs / shorts)
            #pragma unroll
            for (int u = 0; u < 2; u++) {
                CP_ASYNC16(xdst[u] + (uint32_t)(s * 16384 + d * 8192), xsrc[u] + io);
                CP_ASYNC16(adst[u] + (uint32_t)(s * 16384 + d * 8192), asrc[u] + io);
            }
        }
        if (t < 32) CP_ASYNC16(esdst + (uint32_t)(s * 1024), essrc + s * 64);
        CP_COMMIT();
    }

    int buf = 0, wbuf = 2;
    for (int ch = 0; ch < 32; ++ch) {
        CP_WAIT1();
        __syncthreads();   // stage ch ready; all reads of stage ch-1 done

        if (ch <= 29) {
            const int s = ch + 2;
            #pragma unroll
            for (int d = 0; d < 2; d++) {
                const int io = s * 64 + d * 32;
                #pragma unroll
                for (int u = 0; u < 2; u++) {
                    CP_ASYNC16(xdst[u] + (uint32_t)(wbuf * 16384 + d * 8192), xsrc[u] + io);
                    CP_ASYNC16(adst[u] + (uint32_t)(wbuf * 16384 + d * 8192), asrc[u] + io);
                }
            }
            if (t < 32) CP_ASYNC16(esdst + (uint32_t)(wbuf * 1024), essrc + s * 64);
            CP_COMMIT();
            wbuf = (wbuf == 2) ? 0 : wbuf + 1;
        } else {
            CP_COMMIT();
        }

        #pragma unroll
        for (int d = 0; d < 2; d++) {
            const uint32_t esb0 = sb + ES_OFFB + (uint32_t)(buf * 1024 + d * 512 + chead * 128);
            const uint32_t esb2 = esb0 + 256u;
            const uint32_t xtb  = sb + XT_OFFB + (uint32_t)(buf * 16384 + d * 8192 + chead * 4096);
            const uint32_t ahb  = sb + AH_OFFB + (uint32_t)(buf * 16384 + d * 8192);

            #pragma unroll
            for (int ks = 0; ks < 2; ks++) {
                const uint32_t eo = (uint32_t)(ks * 32 + tg * 4);
                uint32_t uesA = lds32u(esb0 + eo);
                uint32_t uesB = lds32u(esb0 + eo + 16u);
                uint32_t ue2A = lds32u(esb2 + eo);
                uint32_t ue2B = lds32u(esb2 + eo + 16u);
                const __half2 esA = *(__half2*)&uesA, esB = *(__half2*)&uesB;
                const __half2 e2A = *(__half2*)&ue2A, e2B = *(__half2*)&ue2B;

                uint32_t aT[4], bT[4];
                #pragma unroll
                for (int r = 0; r < 4; r++) {
                    const uint32_t rb  = ahb + (uint32_t)(rows[r] * 64);
                    const uint32_t sxr = (uint32_t)(((rows[r] >> 1) & 3) << 2);
                    uint32_t mA = lds32u(rb + ((((uint32_t)(ks * 8 + tg)) ^ sxr) << 2));
                    uint32_t mB = lds32u(rb + ((((uint32_t)(ks * 8 + tg + 4)) ^ sxr) << 2));
                    __half2 va = __hmax2(__hmul2(esA, edh[r]), __hmul2(e2A, ed2h[r]));
                    __half2 vb = __hmax2(__hmul2(esB, edh[r]), __hmul2(e2B, ed2h[r]));
                    aT[r] = (*(uint32_t*)&va) & mA;
                    bT[r] = (*(uint32_t*)&vb) & mB;
                }

                #pragma unroll
                for (int nt = 0; nt < 8; nt++) {
                    const int r = nt * 8 + g;
                    const uint32_t g16 = (uint32_t)(ks * 2 + (tg >> 1)) ^ (uint32_t)((r >> 1) & 3);
                    uint2 u = lds64u(xtb + (uint32_t)(r * 64) + g16 * 16u + (uint32_t)((tg & 1) * 8));
                    mma16(acc[0][nt], aT[0], aT[1], bT[0], bT[1], u.x, u.y);
                    mma16(acc[1][nt], aT[2], aT[3], bT[2], bT[3], u.x, u.y);
                }
                mma16(accl[0], aT[0], aT[1], bT[0], bT[1], ONES_H2, ONES_H2);
                mma16(accl[1], aT[2], aT[3], bT[2], bT[3], ONES_H2, ONES_H2);
            }
        }
        buf = (buf == 2) ? 0 : buf + 1;
    }

    // ---- epilogue: normalize, +bias, ELU, store
    const float* bp = bias + (size_t)(h0 + chead) * Cc;
    #pragma unroll
    for (int mt = 0; mt < 2; mt++) {
        const int r0 = ctw * 32 + mt * 16 + g;
        const int r1 = r0 + 8;
        const float inv0 = 1.f / accl[mt][0];
        const float inv1 = 1.f / accl[mt][2];
        float* o0 = out + (bn0 + j0 + r0) * HC + (size_t)(h0 + chead) * Cc;
        float* o1 = out + (bn0 + j0 + r1) * HC + (size_t)(h0 + chead) * Cc;
        #pragma unroll
        for (int nt = 0; nt < 8; nt++) {
            const int c = nt * 8 + tg * 2;
            const float b0v = bp[c], b1v = bp[c + 1];
            float w0 = acc[mt][nt][0] * inv0 + b0v;
            float w1 = acc[mt][nt][1] * inv0 + b1v;
            float w2 = acc[mt][nt][2] * inv1 + b0v;
            float w3 = acc[mt][nt][3] * inv1 + b1v;
            w0 = w0 > 0.f ? w0 : (fexp(w0) - 1.f);
            w1 = w1 > 0.f ? w1 : (fexp(w1) - 1.f);
            w2 = w2 > 0.f ? w2 : (fexp(w2) - 1.f);
            w3 = w3 > 0.f ? w3 : (fexp(w3) - 1.f);
            *(float2*)(o0 + c) = make_float2(w0, w1);
            *(float2*)(o1 + c) = make_float2(w2, w3);
        }
    }
}

// ---------------------------------------------------------------------------
extern "C" void kernel_launch(void* const* d_in, const int* in_sizes, int n_in,
                              void* d_out, int out_size)
{
    const float* feats   = (const float*)d_in[0];
    const int*   adj     = (const int*)  d_in[1];
    const float* W       = (const float*)d_in[2];
    const float* att_src = (const float*)d_in[3];
    const float* att_dst = (const float*)d_in[4];
    const float* bias    = (const float*)d_in[5];
    float*       out     = (float*)d_out;
    (void)in_sizes; (void)n_in; (void)out_size;

    static bool attr_set = false;
    if (!attr_set) {
        cudaFuncSetAttribute(gat_agg_mma,
                             cudaFuncAttributeMaxDynamicSharedMemorySize, AGG_SMEM);
        cudaFuncSetAttribute(gemm_proj_mma,
                             cudaFuncAttributeMaxDynamicSharedMemorySize, PROJ_SMEM);
        attr_set = true;
    }

    pack_adjH<<<dim3(Nn / 32, Nn / 32, Bz), 256>>>(adj);
    gemm_proj_mma<<<dim3((Bz * Nn) / 128, HC / 128), 256, PROJ_SMEM>>>(feats, W);
    att_prep<<<(Bz * Nn) / 8, 256>>>(att_src, att_dst);
    gat_agg_mma<<<dim3(Nn / 128, Hh / 2, Bz), 256, AGG_SMEM>>>(bias, out);
}

// round 15
// speedup vs baseline: 1.2979x; 1.0142x over previous
#include <cuda_runtime.h>
#include <cuda_fp16.h>
#include <cstdint>
#include <math.h>

#define Bz 4
#define Nn 2048
#define Dd 512
#define Hh 8
#define Cc 64
#define HC 512

// ---------------- device scratch ----------------
__device__ __half g_XTh[(size_t)Bz * HC * Nn];   // transposed fp16, i-pair permuted
__device__ __half g_EsH [(size_t)Bz * Hh * Nn];  // exp(s-4)  fp16 [b][h][n]
__device__ __half g_Es2H[(size_t)Bz * Hh * Nn];  // exp(.2s-4) fp16
__device__ float  g_EdT [(size_t)Bz * Hh * Nn];  // exp(d)   fp32
__device__ float  g_Ed2T[(size_t)Bz * Hh * Nn];  // exp(.2d) fp32
__device__ unsigned short g_adjH[(size_t)Bz * Nn * Nn]; // mask [b][j][i] 0xFFFF/0, diag folded

// ---------------- helpers ----------------
__device__ __forceinline__ uint32_t smem_u32(const void* p) {
    uint32_t a;
    asm("{ .reg .u64 t; cvta.to.shared.u64 t, %1; cvt.u32.u64 %0, t; }"
        : "=r"(a) : "l"(p));
    return a;
}
__device__ __forceinline__ uint32_t tf32u(uint32_t x) {
    uint32_t r;
    asm("cvt.rna.tf32.f32 %0, %1;" : "=r"(r) : "f"(__uint_as_float(x)));
    return r;
}
__device__ __forceinline__ uint2 lds64u(uint32_t a) {
    uint2 v;
    asm volatile("ld.shared.v2.u32 {%0,%1}, [%2];"
                 : "=r"(v.x), "=r"(v.y) : "r"(a));
    return v;
}
__device__ __forceinline__ float2 lds64f(uint32_t a) {
    float2 v;
    asm volatile("ld.shared.v2.f32 {%0,%1}, [%2];"
                 : "=f"(v.x), "=f"(v.y) : "r"(a));
    return v;
}
__device__ __forceinline__ uint32_t lds32u(uint32_t a) {
    uint32_t v;
    asm volatile("ld.shared.u32 %0, [%1];" : "=r"(v) : "r"(a));
    return v;
}
__device__ __forceinline__ void sts16(uint32_t a, uint16_t v) {
    asm volatile("st.shared.u16 [%0], %1;" :: "r"(a), "h"(v) : "memory");
}
__device__ __forceinline__ void sts64f(uint32_t a, float2 v) {
    asm volatile("st.shared.v2.f32 [%0], {%1,%2};"
                 :: "r"(a), "f"(v.x), "f"(v.y) : "memory");
}
__device__ __forceinline__ uint16_t f2h(float f) {
    __half h = __float2half_rn(f);
    return *(uint16_t*)&h;
}

#define CP_ASYNC16(dst, src) \
    asm volatile("cp.async.cg.shared.global [%0], [%1], 16;" \
                 :: "r"(dst), "l"(src) : "memory")
#define CP_COMMIT()  asm volatile("cp.async.commit_group;" ::: "memory")
#define CP_WAIT1()   asm volatile("cp.async.wait_group 1;" ::: "memory")
#define CP_WAIT2()   asm volatile("cp.async.wait_group 2;" ::: "memory")

// tf32 mma (proj kernel)
__device__ __forceinline__ void mma8(float* d,
                                     uint32_t a0, uint32_t a1, uint32_t a2, uint32_t a3,
                                     uint32_t b0, uint32_t b1) {
    asm volatile(
        "mma.sync.aligned.m16n8k8.row.col.f32.tf32.tf32.f32 "
        "{%0,%1,%2,%3}, {%4,%5,%6,%7}, {%8,%9}, {%0,%1,%2,%3};"
        : "+f"(d[0]), "+f"(d[1]), "+f"(d[2]), "+f"(d[3])
        : "r"(a0), "r"(a1), "r"(a2), "r"(a3), "r"(b0), "r"(b1));
}
// fp16 mma (agg kernel)
__device__ __forceinline__ void mma16(float* d,
                                      uint32_t a0, uint32_t a1, uint32_t a2, uint32_t a3,
                                      uint32_t b0, uint32_t b1) {
    asm volatile(
        "mma.sync.aligned.m16n8k16.row.col.f32.f16.f16.f32 "
        "{%0,%1,%2,%3}, {%4,%5,%6,%7}, {%8,%9}, {%0,%1,%2,%3};"
        : "+f"(d[0]), "+f"(d[1]), "+f"(d[2]), "+f"(d[3])
        : "r"(a0), "r"(a1), "r"(a2), "r"(a3), "r"(b0), "r"(b1));
}
#define ONES_H2 0x3C003C00u

// ---------------- fast exp (FFMA-only) ----------------
__device__ __forceinline__ float fexp(float x) {
    const float LOG2E = 1.4426950408889634f;
    float t = x * LOG2E;
    float z = t + 12582912.0f;
    int   n = __float_as_int(z) - 0x4B400000;
    float r = z - 12582912.0f;
    float f = t - r;
    float u = f * 0.69314718056f;
    float p = 8.3333333e-3f;
    p = p * u + 4.1666667e-2f;
    p = p * u + 1.6666667e-1f;
    p = p * u + 0.5f;
    p = p * u + 1.0f;
    p = p * u + 1.0f;
    return p * __int_as_float((n + 127) << 23);
}

// ---------------------------------------------------------------------------
// Kernel 1: adjacency -> transposed fp16 AND-mask (diag folded)
// ---------------------------------------------------------------------------
__global__ __launch_bounds__(256) void pack_adjH(const int* __restrict__ adj)
{
    __shared__ unsigned short ts[32][36];
    const int b  = blockIdx.z;
    const int i0 = blockIdx.y * 32;
    const int j0 = blockIdx.x * 32;
    const int t  = threadIdx.x;
    const int r  = t >> 3;
    const int c4 = t & 7;

    int4 v = *(const int4*)(adj + ((size_t)b * Nn + i0 + r) * Nn + j0 + c4 * 4);
    const int ii = i0 + r;
    ts[r][c4 * 4 + 0] = (v.x != 0 || ii == j0 + c4 * 4 + 0) ? 0xFFFFu : 0u;
    ts[r][c4 * 4 + 1] = (v.y != 0 || ii == j0 + c4 * 4 + 1) ? 0xFFFFu : 0u;
    ts[r][c4 * 4 + 2] = (v.z != 0 || ii == j0 + c4 * 4 + 2) ? 0xFFFFu : 0u;
    ts[r][c4 * 4 + 3] = (v.w != 0 || ii == j0 + c4 * 4 + 3) ? 0xFFFFu : 0u;
    __syncthreads();

    const int jr  = t >> 3;
    const int ic4 = t & 7;
    uint32_t lo = (uint32_t)ts[ic4 * 4 + 0][jr] | ((uint32_t)ts[ic4 * 4 + 1][jr] << 16);
    uint32_t hi = (uint32_t)ts[ic4 * 4 + 2][jr] | ((uint32_t)ts[ic4 * 4 + 3][jr] << 16);
    *(uint2*)(g_adjH + ((size_t)b * Nn + j0 + jr) * Nn + i0 + ic4 * 4) =
        make_uint2(lo, hi);
}

// ---------------------------------------------------------------------------
// Kernel 2: projection GEMM (mma.sync tf32, cp.async 4-stage) + FUSED
// epilogues: (a) attention-score reduction -> exp tables (att_prep deleted,
// g_X never materialized), (b) transposed fp16 store -> g_XTh.
// ---------------------------------------------------------------------------
#define PA_OFF 0u
#define PB_OFF 40960u
#define RED_OFF 36864u     // 2 heads x 2 halves x 128 rows x float2 = 8KB (36864..45055)
#define PROJ_SMEM 75776u

__global__ void __launch_bounds__(256, 2) gemm_proj_mma(
    const float* __restrict__ A, const float* __restrict__ Wm,
    const float* __restrict__ att_src, const float* __restrict__ att_dst)
{
    extern __shared__ float sm[];
    const uint32_t sb = smem_u32(sm);

    const int t  = threadIdx.x;
    const int m0 = blockIdx.x * 128;
    const int n0 = blockIdx.y * 128;
    const int wid = t >> 5, lane = t & 31;
    const int wm = wid & 1, wn = wid >> 1;
    const int g = lane >> 2, tg = lane & 3;

    float acc[4][4][4];
    #pragma unroll
    for (int i = 0; i < 4; i++)
        #pragma unroll
        for (int j = 0; j < 4; j++)
            #pragma unroll
            for (int r = 0; r < 4; r++) acc[i][j][r] = 0.f;

    const float* asrc[2]; uint32_t adst[2];
    const float* bsrc[2]; uint32_t bdst[2];
    #pragma unroll
    for (int u = 0; u < 2; u++) {
        int gid = u * 256 + t;
        int ar = gid >> 2, ag = gid & 3;
        asrc[u] = A + (size_t)(m0 + ar) * Dd + ag * 4;
        adst[u] = sb + PA_OFF + (uint32_t)(ar * 80 + ag * 16);
        int br = gid >> 5, bg = gid & 31;
        bsrc[u] = Wm + (size_t)br * HC + n0 + bg * 4;
        bdst[u] = sb + PB_OFF + (uint32_t)(br * 544 + bg * 16);
    }

    #pragma unroll
    for (int s = 0; s < 3; s++) {
        #pragma unroll
        for (int u = 0; u < 2; u++) {
            CP_ASYNC16(adst[u] + s * 10240u, asrc[u] + s * 16);
            CP_ASYNC16(bdst[u] + s * 8704u,  bsrc[u] + (size_t)(s * 16) * HC);
        }
        CP_COMMIT();
    }

    for (int kc = 0; kc < 32; ++kc) {
        const int buf = kc & 3;
        CP_WAIT2();
        __syncthreads();
        if (kc < 29) {
            const int s = (kc + 3) & 3, k0 = (kc + 3) * 16;
            #pragma unroll
            for (int u = 0; u < 2; u++) {
                CP_ASYNC16(adst[u] + s * 10240u, asrc[u] + k0);
                CP_ASYNC16(bdst[u] + s * 8704u,  bsrc[u] + (size_t)k0 * HC);
            }
            CP_COMMIT();
        } else {
            CP_COMMIT();
        }

        const uint32_t Ab = sb + PA_OFF + buf * 10240u + (uint32_t)(wm * 64) * 80u;
        const uint32_t Bb = sb + PB_OFF + buf * 8704u + (uint32_t)(wn * 32) * 4u;

        #pragma unroll
        for (int ks = 0; ks < 2; ks++) {
            uint32_t a[4][4];
            #pragma unroll
            for (int mt = 0; mt < 4; mt++) {
                const uint32_t base = Ab + (uint32_t)((mt * 16 + g) * 80 + (ks * 8 + tg) * 4);
                a[mt][0] = tf32u(lds32u(base));
                a[mt][1] = tf32u(lds32u(base + 640u));
                a[mt][2] = tf32u(lds32u(base + 16u));
                a[mt][3] = tf32u(lds32u(base + 656u));
            }
            uint2 bf[4];
            #pragma unroll
            for (int nt = 0; nt < 4; nt++) {
                const uint32_t base = Bb + (uint32_t)((ks * 8 + tg) * 544 + (nt * 8 + g) * 4);
                bf[nt].x = tf32u(lds32u(base));
                bf[nt].y = tf32u(lds32u(base + 2176u));
            }
            #pragma unroll
            for (int mt = 0; mt < 4; mt++)
                #pragma unroll
                for (int nt = 0; nt < 4; nt++)
                    mma8(acc[mt][nt], a[mt][0], a[mt][1], a[mt][2], a[mt][3],
                         bf[nt].x, bf[nt].y);
        }
    }

    __syncthreads();   // staging buffers fully consumed; SMEM reusable

    // ---- epilogue A: per-row attention dots from registers
    // thread's 8 columns (global hc): n0 + wn*32 + nt*8 + tg*2 + {0,1}
    {
        float s[4][2], dd[4][2];
        #pragma unroll
        for (int mt = 0; mt < 4; mt++) {
            s[mt][0] = s[mt][1] = 0.f;
            dd[mt][0] = dd[mt][1] = 0.f;
        }
        const int cbase = n0 + wn * 32 + tg * 2;
        #pragma unroll
        for (int nt = 0; nt < 4; nt++) {
            const float a0 = __ldg(att_src + cbase + nt * 8);
            const float a1 = __ldg(att_src + cbase + nt * 8 + 1);
            const float d0 = __ldg(att_dst + cbase + nt * 8);
            const float d1 = __ldg(att_dst + cbase + nt * 8 + 1);
            #pragma unroll
            for (int mt = 0; mt < 4; mt++) {
                s[mt][0]  += acc[mt][nt][0] * a0 + acc[mt][nt][1] * a1;
                s[mt][1]  += acc[mt][nt][2] * a0 + acc[mt][nt][3] * a1;
                dd[mt][0] += acc[mt][nt][0] * d0 + acc[mt][nt][1] * d1;
                dd[mt][1] += acc[mt][nt][2] * d0 + acc[mt][nt][3] * d1;
            }
        }
        // quad reduce over tg (lanes g*4+tg; xor 1,2 stay in quad)
        #pragma unroll
        for (int o = 1; o < 4; o <<= 1) {
            #pragma unroll
            for (int mt = 0; mt < 4; mt++) {
                s[mt][0]  += __shfl_xor_sync(0xffffffffu, s[mt][0], o);
                s[mt][1]  += __shfl_xor_sync(0xffffffffu, s[mt][1], o);
                dd[mt][0] += __shfl_xor_sync(0xffffffffu, dd[mt][0], o);
                dd[mt][1] += __shfl_xor_sync(0xffffffffu, dd[mt][1], o);
            }
        }
        if (tg == 0) {
            const int hh = wn >> 1, half = wn & 1;
            #pragma unroll
            for (int mt = 0; mt < 4; mt++) {
                #pragma unroll
                for (int rh = 0; rh < 2; rh++) {
                    const int r = wm * 64 + mt * 16 + rh * 8 + g;
                    sts64f(sb + RED_OFF + (uint32_t)(((hh * 2 + half) * 128 + r) * 8),
                           make_float2(s[mt][rh], dd[mt][rh]));
                }
            }
        }
    }

    // ---- epilogue B stage: transpose acc -> fp16 staging (disjoint SMEM region)
    #pragma unroll
    for (int mt = 0; mt < 4; mt++) {
        const int ml = wm * 64 + mt * 16 + g;
        #pragma unroll
        for (int nt = 0; nt < 4; nt++) {
            const int hcl = wn * 32 + nt * 8 + tg * 2;
            sts16(sb + (uint32_t)(hcl * 272 + ml * 2),             f2h(acc[mt][nt][0]));
            sts16(sb + (uint32_t)((hcl + 1) * 272 + ml * 2),       f2h(acc[mt][nt][1]));
            sts16(sb + (uint32_t)(hcl * 272 + (ml + 8) * 2),       f2h(acc[mt][nt][2]));
            sts16(sb + (uint32_t)((hcl + 1) * 272 + (ml + 8) * 2), f2h(acc[mt][nt][3]));
        }
    }
    __syncthreads();

    const int bb = m0 >> 11, mloc = m0 & 2047;

    // ---- epilogue A finish: reduce halves, exp, store tables
    {
        const int hh = t & 1, m = t >> 1;
        float2 pA = lds64f(sb + RED_OFF + (uint32_t)(((hh * 2 + 0) * 128 + m) * 8));
        float2 pB = lds64f(sb + RED_OFF + (uint32_t)(((hh * 2 + 1) * 128 + m) * 8));
        const float s = pA.x + pB.x;
        const float d = pA.y + pB.y;
        const int h = blockIdx.y * 2 + hh;
        const size_t o = ((size_t)bb * Hh + h) * Nn + mloc + m;
        g_EsH [o] = __float2half_rn(fexp(s - 4.0f));
        g_Es2H[o] = __float2half_rn(fexp(0.2f * s - 4.0f));
        g_EdT [o] = fexp(d);
        g_Ed2T[o] = fexp(0.2f * d);
    }

    // ---- epilogue B finish: permuted fp16 transpose out
    #pragma unroll 1
    for (int pass = 0; pass < 16; pass++) {
        const int row = pass * 8 + (t >> 5);
        const int ln  = t & 31;
        __half* orow = g_XTh + ((size_t)bb * HC + n0 + row) * Nn + mloc;
        #pragma unroll
        for (int k = 0; k < 2; k++) {
            const int wi = ln + k * 32;
            const int w16 = wi & 15, grp = wi >> 4;
            const int p16 = (w16 & 8) | ((w16 & 3) << 1) | ((w16 >> 2) & 1);
            uint32_t v = lds32u(sb + (uint32_t)(row * 272 + wi * 4));
            *(uint32_t*)(orow + (grp * 16 + p16) * 2) = v;
        }
    }
}

// ---------------------------------------------------------------------------
// Kernel 3: fused masked-softmax aggregation (unchanged from R14 — proven)
// ---------------------------------------------------------------------------
#define XT_OFFB  0u        // 3 stages x 16384B (2 subs x 128 rows x 64B)
#define AH_OFFB  49152u    // 3 stages x 16384B
#define ES_OFFB  98304u    // 3 stages x 1024B (sub*512 + var*256 + head*128)
#define AGG_SMEM 101376u

__global__ void __launch_bounds__(256, 2) gat_agg_mma(
    const float* __restrict__ bias, float* __restrict__ out)
{
    extern __shared__ float sm[];
    const uint32_t sb = smem_u32(sm);

    const int t  = threadIdx.x;
    const int b  = blockIdx.z;
    const int h0 = blockIdx.y * 2;
    const int j0 = blockIdx.x * 128;

    const int wid = t >> 5, lane = t & 31;
    const int chead = wid >> 2, ctw = wid & 3;
    const int g = lane >> 2, tg = lane & 3;

    const size_t bn0 = (size_t)b * Nn;
    const size_t edb = ((size_t)b * Hh + h0 + chead) * Nn + j0;

    int rows[4]; __half2 edh[4], ed2h[4];
    #pragma unroll
    for (int r = 0; r < 4; r++) {
        rows[r] = ctw * 32 + (r >> 1) * 16 + (r & 1) * 8 + g;
        edh[r]  = __half2half2(__float2half_rn(g_EdT [edb + rows[r]]));
        ed2h[r] = __half2half2(__float2half_rn(g_Ed2T[edb + rows[r]]));
    }

    float acc[2][8][4];
    #pragma unroll
    for (int m = 0; m < 2; m++)
        #pragma unroll
        for (int n = 0; n < 8; n++)
            #pragma unroll
            for (int r = 0; r < 4; r++) acc[m][n][r] = 0.f;
    float accl[2][4];
    #pragma unroll
    for (int m = 0; m < 2; m++)
        #pragma unroll
        for (int r = 0; r < 4; r++) accl[m][r] = 0.f;

    const __half* xsrc[2]; uint32_t xdst[2];
    const unsigned short* asrc[2]; uint32_t adst[2];
    #pragma unroll
    for (int u = 0; u < 2; u++) {
        int gid = u * 256 + t;
        int row = gid >> 2, q = gid & 3;
        int hh = row >> 6, c = row & 63;
        xsrc[u] = g_XTh + ((size_t)b * HC + (size_t)(h0 + hh) * Cc + c) * Nn + q * 8;
        xdst[u] = sb + XT_OFFB + (uint32_t)(row * 64 + ((q ^ ((row >> 1) & 3)) << 4));
        asrc[u] = g_adjH + (bn0 + j0 + row) * Nn + q * 8;
        adst[u] = sb + AH_OFFB + (uint32_t)(row * 64 + ((q ^ ((row >> 1) & 3)) << 4));
    }
    const __half* essrc = nullptr; uint32_t esdst = 0;
    if (t < 32) {
        int sub = t >> 4, tt = t & 15;
        int seg = tt >> 2, gi = tt & 3;
        int var = seg >> 1, hh = seg & 1;
        const __half* tbl = var ? g_Es2H : g_EsH;
        essrc = tbl + ((size_t)b * Hh + h0 + hh) * Nn + sub * 32 + gi * 8;
        esdst = sb + ES_OFFB + (uint32_t)(sub * 512 + var * 256 + hh * 128 + gi * 16);
    }

    #pragma unroll
    for (int s = 0; s < 2; s++) {
        #pragma unroll
        for (int d = 0; d < 2; d++) {
            const int io = s * 64 + d * 32;
            #pragma unroll
            for (int u = 0; u < 2; u++) {
                CP_ASYNC16(xdst[u] + (uint32_t)(s * 16384 + d * 8192), xsrc[u] + io);
                CP_ASYNC16(adst[u] + (uint32_t)(s * 16384 + d * 8192), asrc[u] + io);
            }
        }
        if (t < 32) CP_ASYNC16(esdst + (uint32_t)(s * 1024), essrc + s * 64);
        CP_COMMIT();
    }

    int buf = 0, wbuf = 2;
    for (int ch = 0; ch < 32; ++ch) {
        CP_WAIT1();
        __syncthreads();

        if (ch <= 29) {
            const int s = ch + 2;
            #pragma unroll
            for (int d = 0; d < 2; d++) {
                const int io = s * 64 + d * 32;
                #pragma unroll
                for (int u = 0; u < 2; u++) {
                    CP_ASYNC16(xdst[u] + (uint32_t)(wbuf * 16384 + d * 8192), xsrc[u] + io);
                    CP_ASYNC16(adst[u] + (uint32_t)(wbuf * 16384 + d * 8192), asrc[u] + io);
                }
            }
            if (t < 32) CP_ASYNC16(esdst + (uint32_t)(wbuf * 1024), essrc + s * 64);
            CP_COMMIT();
            wbuf = (wbuf == 2) ? 0 : wbuf + 1;
        } else {
            CP_COMMIT();
        }

        #pragma unroll
        for (int d = 0; d < 2; d++) {
            const uint32_t esb0 = sb + ES_OFFB + (uint32_t)(buf * 1024 + d * 512 + chead * 128);
            const uint32_t esb2 = esb0 + 256u;
            const uint32_t xtb  = sb + XT_OFFB + (uint32_t)(buf * 16384 + d * 8192 + chead * 4096);
            const uint32_t ahb  = sb + AH_OFFB + (uint32_t)(buf * 16384 + d * 8192);

            #pragma unroll
            for (int ks = 0; ks < 2; ks++) {
                const uint32_t eo = (uint32_t)(ks * 32 + tg * 4);
                uint32_t uesA = lds32u(esb0 + eo);
                uint32_t uesB = lds32u(esb0 + eo + 16u);
                uint32_t ue2A = lds32u(esb2 + eo);
                uint32_t ue2B = lds32u(esb2 + eo + 16u);
                const __half2 esA = *(__half2*)&uesA, esB = *(__half2*)&uesB;
                const __half2 e2A = *(__half2*)&ue2A, e2B = *(__half2*)&ue2B;

                uint32_t aT[4], bT[4];
                #pragma unroll
                for (int r = 0; r < 4; r++) {
                    const uint32_t rb  = ahb + (uint32_t)(rows[r] * 64);
                    const uint32_t sxr = (uint32_t)(((rows[r] >> 1) & 3) << 2);
                    uint32_t mA = lds32u(rb + ((((uint32_t)(ks * 8 + tg)) ^ sxr) << 2));
                    uint32_t mB = lds32u(rb + ((((uint32_t)(ks * 8 + tg + 4)) ^ sxr) << 2));
                    __half2 va = __hmax2(__hmul2(esA, edh[r]), __hmul2(e2A, ed2h[r]));
                    __half2 vb = __hmax2(__hmul2(esB, edh[r]), __hmul2(e2B, ed2h[r]));
                    aT[r] = (*(uint32_t*)&va) & mA;
                    bT[r] = (*(uint32_t*)&vb) & mB;
                }

                #pragma unroll
                for (int nt = 0; nt < 8; nt++) {
                    const int r = nt * 8 + g;
                    const uint32_t g16 = (uint32_t)(ks * 2 + (tg >> 1)) ^ (uint32_t)((r >> 1) & 3);
                    uint2 u = lds64u(xtb + (uint32_t)(r * 64) + g16 * 16u + (uint32_t)((tg & 1) * 8));
                    mma16(acc[0][nt], aT[0], aT[1], bT[0], bT[1], u.x, u.y);
                    mma16(acc[1][nt], aT[2], aT[3], bT[2], bT[3], u.x, u.y);
                }
                mma16(accl[0], aT[0], aT[1], bT[0], bT[1], ONES_H2, ONES_H2);
                mma16(accl[1], aT[2], aT[3], bT[2], bT[3], ONES_H2, ONES_H2);
            }
        }
        buf = (buf == 2) ? 0 : buf + 1;
    }

    // ---- epilogue: normalize, +bias, ELU, store
    const float* bp = bias + (size_t)(h0 + chead) * Cc;
    #pragma unroll
    for (int mt = 0; mt < 2; mt++) {
        const int r0 = ctw * 32 + mt * 16 + g;
        const int r1 = r0 + 8;
        const float inv0 = 1.f / accl[mt][0];
        const float inv1 = 1.f / accl[mt][2];
        float* o0 = out + (bn0 + j0 + r0) * HC + (size_t)(h0 + chead) * Cc;
        float* o1 = out + (bn0 + j0 + r1) * HC + (size_t)(h0 + chead) * Cc;
        #pragma unroll
        for (int nt = 0; nt < 8; nt++) {
            const int c = nt * 8 + tg * 2;
            const float b0v = bp[c], b1v = bp[c + 1];
            float w0 = acc[mt][nt][0] * inv0 + b0v;
            float w1 = acc[mt][nt][1] * inv0 + b1v;
            float w2 = acc[mt][nt][2] * inv1 + b0v;
            float w3 = acc[mt][nt][3] * inv1 + b1v;
            w0 = w0 > 0.f ? w0 : (fexp(w0) - 1.f);
            w1 = w1 > 0.f ? w1 : (fexp(w1) - 1.f);
            w2 = w2 > 0.f ? w2 : (fexp(w2) - 1.f);
            w3 = w3 > 0.f ? w3 : (fexp(w3) - 1.f);
            *(float2*)(o0 + c) = make_float2(w0, w1);
            *(float2*)(o1 + c) = make_float2(w2, w3);
        }
    }
}

// ---------------------------------------------------------------------------
extern "C" void kernel_launch(void* const* d_in, const int* in_sizes, int n_in,
                              void* d_out, int out_size)
{
    const float* feats   = (const float*)d_in[0];
    const int*   adj     = (const int*)  d_in[1];
    const float* W       = (const float*)d_in[2];
    const float* att_src = (const float*)d_in[3];
    const float* att_dst = (const float*)d_in[4];
    const float* bias    = (const float*)d_in[5];
    float*       out     = (float*)d_out;
    (void)in_sizes; (void)n_in; (void)out_size;

    static bool attr_set = false;
    if (!attr_set) {
        cudaFuncSetAttribute(gat_agg_mma,
                             cudaFuncAttributeMaxDynamicSharedMemorySize, AGG_SMEM);
        cudaFuncSetAttribute(gemm_proj_mma,
                             cudaFuncAttributeMaxDynamicSharedMemorySize, PROJ_SMEM);
        attr_set = true;
    }

    pack_adjH<<<dim3(Nn / 32, Nn / 32, Bz), 256>>>(adj);
    gemm_proj_mma<<<dim3((Bz * Nn) / 128, HC / 128), 256, PROJ_SMEM>>>(
        feats, W, att_src, att_dst);
    gat_agg_mma<<<dim3(Nn / 128, Hh / 2, Bz), 256, AGG_SMEM>>>(bias, out);
}

// round 16
// speedup vs baseline: 1.3331x; 1.0271x over previous
#include <cuda_runtime.h>
#include <cuda_fp16.h>
#include <cstdint>
#include <math.h>

#define Bz 4
#define Nn 2048
#define Dd 512
#define Hh 8
#define Cc 64
#define HC 512

// ---------------- device scratch ----------------
__device__ __half g_Ah [(size_t)Bz * Nn * Dd];   // feats fp16 [B*N, D]
__device__ __half g_WtH[(size_t)HC * Dd];        // W transposed fp16 [n][k]
__device__ __half g_XTh[(size_t)Bz * HC * Nn];   // x transposed fp16, i-pair permuted
__device__ __half g_EsH [(size_t)Bz * Hh * Nn];  // exp(s-4)  fp16 [b][h][n]
__device__ __half g_Es2H[(size_t)Bz * Hh * Nn];  // exp(.2s-4) fp16
__device__ float  g_EdT [(size_t)Bz * Hh * Nn];  // exp(d)   fp32
__device__ float  g_Ed2T[(size_t)Bz * Hh * Nn];  // exp(.2d) fp32
__device__ unsigned short g_adjH[(size_t)Bz * Nn * Nn]; // mask [b][j][i] 0xFFFF/0, diag folded

// ---------------- helpers ----------------
__device__ __forceinline__ uint32_t smem_u32(const void* p) {
    uint32_t a;
    asm("{ .reg .u64 t; cvta.to.shared.u64 t, %1; cvt.u32.u64 %0, t; }"
        : "=r"(a) : "l"(p));
    return a;
}
__device__ __forceinline__ uint2 lds64u(uint32_t a) {
    uint2 v;
    asm volatile("ld.shared.v2.u32 {%0,%1}, [%2];"
                 : "=r"(v.x), "=r"(v.y) : "r"(a));
    return v;
}
__device__ __forceinline__ float2 lds64f(uint32_t a) {
    float2 v;
    asm volatile("ld.shared.v2.f32 {%0,%1}, [%2];"
                 : "=f"(v.x), "=f"(v.y) : "r"(a));
    return v;
}
__device__ __forceinline__ uint32_t lds32u(uint32_t a) {
    uint32_t v;
    asm volatile("ld.shared.u32 %0, [%1];" : "=r"(v) : "r"(a));
    return v;
}
__device__ __forceinline__ void sts16(uint32_t a, uint16_t v) {
    asm volatile("st.shared.u16 [%0], %1;" :: "r"(a), "h"(v) : "memory");
}
__device__ __forceinline__ void sts64f(uint32_t a, float2 v) {
    asm volatile("st.shared.v2.f32 [%0], {%1,%2};"
                 :: "r"(a), "f"(v.x), "f"(v.y) : "memory");
}
__device__ __forceinline__ uint16_t f2h(float f) {
    __half h = __float2half_rn(f);
    return *(uint16_t*)&h;
}

#define CP_ASYNC16(dst, src) \
    asm volatile("cp.async.cg.shared.global [%0], [%1], 16;" \
                 :: "r"(dst), "l"(src) : "memory")
#define CP_COMMIT()  asm volatile("cp.async.commit_group;" ::: "memory")
#define CP_WAIT1()   asm volatile("cp.async.wait_group 1;" ::: "memory")
#define CP_WAIT2()   asm volatile("cp.async.wait_group 2;" ::: "memory")

// fp16 mma (both kernels now)
__device__ __forceinline__ void mma16(float* d,
                                      uint32_t a0, uint32_t a1, uint32_t a2, uint32_t a3,
                                      uint32_t b0, uint32_t b1) {
    asm volatile(
        "mma.sync.aligned.m16n8k16.row.col.f32.f16.f16.f32 "
        "{%0,%1,%2,%3}, {%4,%5,%6,%7}, {%8,%9}, {%0,%1,%2,%3};"
        : "+f"(d[0]), "+f"(d[1]), "+f"(d[2]), "+f"(d[3])
        : "r"(a0), "r"(a1), "r"(a2), "r"(a3), "r"(b0), "r"(b1));
}
#define ONES_H2 0x3C003C00u

// ---------------- fast exp (FFMA-only) ----------------
__device__ __forceinline__ float fexp(float x) {
    const float LOG2E = 1.4426950408889634f;
    float t = x * LOG2E;
    float z = t + 12582912.0f;
    int   n = __float_as_int(z) - 0x4B400000;
    float r = z - 12582912.0f;
    float f = t - r;
    float u = f * 0.69314718056f;
    float p = 8.3333333e-3f;
    p = p * u + 4.1666667e-2f;
    p = p * u + 1.6666667e-1f;
    p = p * u + 0.5f;
    p = p * u + 1.0f;
    p = p * u + 1.0f;
    return p * __int_as_float((n + 127) << 23);
}

// ---------------------------------------------------------------------------
// Kernel 0a: feats fp32 -> fp16
// ---------------------------------------------------------------------------
__global__ __launch_bounds__(256) void h16_feats(const float* __restrict__ A)
{
    const int i = blockIdx.x * 256 + threadIdx.x;   // 8 halfs per thread
    const float4 v0 = *(const float4*)(A + (size_t)i * 8);
    const float4 v1 = *(const float4*)(A + (size_t)i * 8 + 4);
    __half2 h0 = __floats2half2_rn(v0.x, v0.y);
    __half2 h1 = __floats2half2_rn(v0.z, v0.w);
    __half2 h2 = __floats2half2_rn(v1.x, v1.y);
    __half2 h3 = __floats2half2_rn(v1.z, v1.w);
    uint4 o = make_uint4(*(uint32_t*)&h0, *(uint32_t*)&h1,
                         *(uint32_t*)&h2, *(uint32_t*)&h3);
    *(uint4*)(g_Ah + (size_t)i * 8) = o;
}

// ---------------------------------------------------------------------------
// Kernel 0b: W [k][n] fp32 -> Wt [n][k] fp16 (tiled transpose)
// ---------------------------------------------------------------------------
__global__ __launch_bounds__(256) void h16_wt(const float* __restrict__ Wm)
{
    __shared__ float ts[32][33];
    const int k0 = blockIdx.x << 5;
    const int n0 = blockIdx.y << 5;
    const int r  = threadIdx.x >> 5;
    const int cl = threadIdx.x & 31;
    #pragma unroll
    for (int rr = 0; rr < 32; rr += 8)
        ts[r + rr][cl] = Wm[(size_t)(k0 + r + rr) * HC + n0 + cl];
    __syncthreads();
    #pragma unroll
    for (int rr = 0; rr < 32; rr += 8)
        g_WtH[(size_t)(n0 + r + rr) * Dd + k0 + cl] = __float2half_rn(ts[cl][r + rr]);
}

// ---------------------------------------------------------------------------
// Kernel 1: adjacency -> transposed fp16 AND-mask (diag folded) — unchanged
// ---------------------------------------------------------------------------
__global__ __launch_bounds__(256) void pack_adjH(const int* __restrict__ adj)
{
    __shared__ unsigned short ts[32][36];
    const int b  = blockIdx.z;
    const int i0 = blockIdx.y * 32;
    const int j0 = blockIdx.x * 32;
    const int t  = threadIdx.x;
    const int r  = t >> 3;
    const int c4 = t & 7;

    int4 v = *(const int4*)(adj + ((size_t)b * Nn + i0 + r) * Nn + j0 + c4 * 4);
    const int ii = i0 + r;
    ts[r][c4 * 4 + 0] = (v.x != 0 || ii == j0 + c4 * 4 + 0) ? 0xFFFFu : 0u;
    ts[r][c4 * 4 + 1] = (v.y != 0 || ii == j0 + c4 * 4 + 1) ? 0xFFFFu : 0u;
    ts[r][c4 * 4 + 2] = (v.z != 0 || ii == j0 + c4 * 4 + 2) ? 0xFFFFu : 0u;
    ts[r][c4 * 4 + 3] = (v.w != 0 || ii == j0 + c4 * 4 + 3) ? 0xFFFFu : 0u;
    __syncthreads();

    const int jr  = t >> 3;
    const int ic4 = t & 7;
    uint32_t lo = (uint32_t)ts[ic4 * 4 + 0][jr] | ((uint32_t)ts[ic4 * 4 + 1][jr] << 16);
    uint32_t hi = (uint32_t)ts[ic4 * 4 + 2][jr] | ((uint32_t)ts[ic4 * 4 + 3][jr] << 16);
    *(uint2*)(g_adjH + ((size_t)b * Nn + j0 + jr) * Nn + i0 + ic4 * 4) =
        make_uint2(lo, hi);
}

// ---------------------------------------------------------------------------
// Kernel 2: projection GEMM — fp16 m16n8k16 (4x tensor rate vs tf32 k8),
// zero in-loop cvt, 8KB/stage staging. Fused epilogues unchanged:
// (a) attention dots -> exp tables, (b) permuted fp16 transpose -> g_XTh.
// ---------------------------------------------------------------------------
#define PA_OFF 0u          // 4 stages x 4096B (128 rows x 32B)
#define PB_OFF 16384u      // 4 stages x 4096B
#define RED_OFF 36864u     // epilogue A reduce region (after staging dead)
#define PROJ_SMEM 46080u

__global__ void __launch_bounds__(256, 2) gemm_proj_mma(
    const float* __restrict__ att_src, const float* __restrict__ att_dst)
{
    extern __shared__ float sm[];
    const uint32_t sb = smem_u32(sm);

    const int t  = threadIdx.x;
    const int m0 = blockIdx.x * 128;
    const int n0 = blockIdx.y * 128;
    const int wid = t >> 5, lane = t & 31;
    const int wm = wid & 1, wn = wid >> 1;
    const int g = lane >> 2, tg = lane & 3;

    float acc[4][4][4];
    #pragma unroll
    for (int i = 0; i < 4; i++)
        #pragma unroll
        for (int j = 0; j < 4; j++)
            #pragma unroll
            for (int r = 0; r < 4; r++) acc[i][j][r] = 0.f;

    // cp.async: 256 granules per stage each for A and B; thread: row=t>>1, q=t&1
    const int crow = t >> 1, cq = t & 1;
    const __half* aSrc = g_Ah  + (size_t)(m0 + crow) * Dd + cq * 8;   // + k0
    const __half* bSrc = g_WtH + (size_t)(n0 + crow) * Dd + cq * 8;   // + k0
    const uint32_t aDst = sb + PA_OFF + (uint32_t)(crow * 32 + cq * 16);
    const uint32_t bDst = sb + PB_OFF + (uint32_t)(crow * 32 + cq * 16);

    #pragma unroll
    for (int s = 0; s < 3; s++) {
        CP_ASYNC16(aDst + s * 4096u, aSrc + s * 16);
        CP_ASYNC16(bDst + s * 4096u, bSrc + s * 16);
        CP_COMMIT();
    }

    for (int kc = 0; kc < 32; ++kc) {
        const int buf = kc & 3;
        CP_WAIT2();
        __syncthreads();
        if (kc < 29) {
            const int s = (kc + 3) & 3, k0 = (kc + 3) * 16;
            CP_ASYNC16(aDst + s * 4096u, aSrc + k0);
            CP_ASYNC16(bDst + s * 4096u, bSrc + k0);
            CP_COMMIT();
        } else {
            CP_COMMIT();
        }

        const uint32_t Ab = sb + PA_OFF + buf * 4096u + (uint32_t)(wm * 64 * 32 + tg * 4);
        const uint32_t Bb = sb + PB_OFF + buf * 4096u + (uint32_t)(wn * 32 * 32 + tg * 4);

        uint32_t a[4][4];
        #pragma unroll
        for (int mt = 0; mt < 4; mt++) {
            const uint32_t base = Ab + (uint32_t)((mt * 16 + g) * 32);
            a[mt][0] = lds32u(base);            // row, k=2tg..
            a[mt][1] = lds32u(base + 256u);     // row+8
            a[mt][2] = lds32u(base + 16u);      // k+8
            a[mt][3] = lds32u(base + 272u);
        }
        uint2 bf[4];
        #pragma unroll
        for (int nt = 0; nt < 4; nt++) {
            const uint32_t base = Bb + (uint32_t)((nt * 8 + g) * 32);
            bf[nt].x = lds32u(base);
            bf[nt].y = lds32u(base + 16u);
        }
        #pragma unroll
        for (int mt = 0; mt < 4; mt++)
            #pragma unroll
            for (int nt = 0; nt < 4; nt++)
                mma16(acc[mt][nt], a[mt][0], a[mt][1], a[mt][2], a[mt][3],
                      bf[nt].x, bf[nt].y);
    }

    __syncthreads();   // staging dead; SMEM reusable

    // ---- epilogue A: per-row attention dots from registers
    {
        float s[4][2], dd[4][2];
        #pragma unroll
        for (int mt = 0; mt < 4; mt++) {
            s[mt][0] = s[mt][1] = 0.f;
            dd[mt][0] = dd[mt][1] = 0.f;
        }
        const int cbase = n0 + wn * 32 + tg * 2;
        #pragma unroll
        for (int nt = 0; nt < 4; nt++) {
            const float a0 = __ldg(att_src + cbase + nt * 8);
            const float a1 = __ldg(att_src + cbase + nt * 8 + 1);
            const float d0 = __ldg(att_dst + cbase + nt * 8);
            const float d1 = __ldg(att_dst + cbase + nt * 8 + 1);
            #pragma unroll
            for (int mt = 0; mt < 4; mt++) {
                s[mt][0]  += acc[mt][nt][0] * a0 + acc[mt][nt][1] * a1;
                s[mt][1]  += acc[mt][nt][2] * a0 + acc[mt][nt][3] * a1;
                dd[mt][0] += acc[mt][nt][0] * d0 + acc[mt][nt][1] * d1;
                dd[mt][1] += acc[mt][nt][2] * d0 + acc[mt][nt][3] * d1;
            }
        }
        #pragma unroll
        for (int o = 1; o < 4; o <<= 1) {
            #pragma unroll
            for (int mt = 0; mt < 4; mt++) {
                s[mt][0]  += __shfl_xor_sync(0xffffffffu, s[mt][0], o);
                s[mt][1]  += __shfl_xor_sync(0xffffffffu, s[mt][1], o);
                dd[mt][0] += __shfl_xor_sync(0xffffffffu, dd[mt][0], o);
                dd[mt][1] += __shfl_xor_sync(0xffffffffu, dd[mt][1], o);
            }
        }
        if (tg == 0) {
            const int hh = wn >> 1, half = wn & 1;
            #pragma unroll
            for (int mt = 0; mt < 4; mt++) {
                #pragma unroll
                for (int rh = 0; rh < 2; rh++) {
                    const int r = wm * 64 + mt * 16 + rh * 8 + g;
                    sts64f(sb + RED_OFF + (uint32_t)(((hh * 2 + half) * 128 + r) * 8),
                           make_float2(s[mt][rh], dd[mt][rh]));
                }
            }
        }
    }

    // ---- epilogue B stage: transpose acc -> fp16 staging
    #pragma unroll
    for (int mt = 0; mt < 4; mt++) {
        const int ml = wm * 64 + mt * 16 + g;
        #pragma unroll
        for (int nt = 0; nt < 4; nt++) {
            const int hcl = wn * 32 + nt * 8 + tg * 2;
            sts16(sb + (uint32_t)(hcl * 272 + ml * 2),             f2h(acc[mt][nt][0]));
            sts16(sb + (uint32_t)((hcl + 1) * 272 + ml * 2),       f2h(acc[mt][nt][1]));
            sts16(sb + (uint32_t)(hcl * 272 + (ml + 8) * 2),       f2h(acc[mt][nt][2]));
            sts16(sb + (uint32_t)((hcl + 1) * 272 + (ml + 8) * 2), f2h(acc[mt][nt][3]));
        }
    }
    __syncthreads();

    const int bb = m0 >> 11, mloc = m0 & 2047;

    // ---- epilogue A finish: reduce halves, exp, store tables
    {
        const int hh = t & 1, m = t >> 1;
        float2 pA = lds64f(sb + RED_OFF + (uint32_t)(((hh * 2 + 0) * 128 + m) * 8));
        float2 pB = lds64f(sb + RED_OFF + (uint32_t)(((hh * 2 + 1) * 128 + m) * 8));
        const float s = pA.x + pB.x;
        const float d = pA.y + pB.y;
        const int h = blockIdx.y * 2 + hh;
        const size_t o = ((size_t)bb * Hh + h) * Nn + mloc + m;
        g_EsH [o] = __float2half_rn(fexp(s - 4.0f));
        g_Es2H[o] = __float2half_rn(fexp(0.2f * s - 4.0f));
        g_EdT [o] = fexp(d);
        g_Ed2T[o] = fexp(0.2f * d);
    }

    // ---- epilogue B finish: permuted fp16 transpose out
    #pragma unroll 1
    for (int pass = 0; pass < 16; pass++) {
        const int row = pass * 8 + (t >> 5);
        const int ln  = t & 31;
        __half* orow = g_XTh + ((size_t)bb * HC + n0 + row) * Nn + mloc;
        #pragma unroll
        for (int k = 0; k < 2; k++) {
            const int wi = ln + k * 32;
            const int w16 = wi & 15, grp = wi >> 4;
            const int p16 = (w16 & 8) | ((w16 & 3) << 1) | ((w16 >> 2) & 1);
            uint32_t v = lds32u(sb + (uint32_t)(row * 272 + wi * 4));
            *(uint32_t*)(orow + (grp * 16 + p16) * 2) = v;
        }
    }
}

// ---------------------------------------------------------------------------
// Kernel 3: fused masked-softmax aggregation (unchanged — proven R14/15)
// ---------------------------------------------------------------------------
#define XT_OFFB  0u
#define AH_OFFB  49152u
#define ES_OFFB  98304u
#define AGG_SMEM 101376u

__global__ void __launch_bounds__(256, 2) gat_agg_mma(
    const float* __restrict__ bias, float* __restrict__ out)
{
    extern __shared__ float sm[];
    const uint32_t sb = smem_u32(sm);

    const int t  = threadIdx.x;
    const int b  = blockIdx.z;
    const int h0 = blockIdx.y * 2;
    const int j0 = blockIdx.x * 128;

    const int wid = t >> 5, lane = t & 31;
    const int chead = wid >> 2, ctw = wid & 3;
    const int g = lane >> 2, tg = lane & 3;

    const size_t bn0 = (size_t)b * Nn;
    const size_t edb = ((size_t)b * Hh + h0 + chead) * Nn + j0;

    int rows[4]; __half2 edh[4], ed2h[4];
    #pragma unroll
    for (int r = 0; r < 4; r++) {
        rows[r] = ctw * 32 + (r >> 1) * 16 + (r & 1) * 8 + g;
        edh[r]  = __half2half2(__float2half_rn(g_EdT [edb + rows[r]]));
        ed2h[r] = __half2half2(__float2half_rn(g_Ed2T[edb + rows[r]]));
    }

    float acc[2][8][4];
    #pragma unroll
    for (int m = 0; m < 2; m++)
        #pragma unroll
        for (int n = 0; n < 8; n++)
            #pragma unroll
            for (int r = 0; r < 4; r++) acc[m][n][r] = 0.f;
    float accl[2][4];
    #pragma unroll
    for (int m = 0; m < 2; m++)
        #pragma unroll
        for (int r = 0; r < 4; r++) accl[m][r] = 0.f;

    const __half* xsrc[2]; uint32_t xdst[2];
    const unsigned short* asrc[2]; uint32_t adst[2];
    #pragma unroll
    for (int u = 0; u < 2; u++) {
        int gid = u * 256 + t;
        int row = gid >> 2, q = gid & 3;
        int hh = row >> 6, c = row & 63;
        xsrc[u] = g_XTh + ((size_t)b * HC + (size_t)(h0 + hh) * Cc + c) * Nn + q * 8;
        xdst[u] = sb + XT_OFFB + (uint32_t)(row * 64 + ((q ^ ((row >> 1) & 3)) << 4));
        asrc[u] = g_adjH + (bn0 + j0 + row) * Nn + q * 8;
        adst[u] = sb + AH_OFFB + (uint32_t)(row * 64 + ((q ^ ((row >> 1) & 3)) << 4));
    }
    const __half* essrc = nullptr; uint32_t esdst = 0;
    if (t < 32) {
        int sub = t >> 4, tt = t & 15;
        int seg = tt >> 2, gi = tt & 3;
        int var = seg >> 1, hh = seg & 1;
        const __half* tbl = var ? g_Es2H : g_EsH;
        essrc = tbl + ((size_t)b * Hh + h0 + hh) * Nn + sub * 32 + gi * 8;
        esdst = sb + ES_OFFB + (uint32_t)(sub * 512 + var * 256 + hh * 128 + gi * 16);
    }

    #pragma unroll
    for (int s = 0; s < 2; s++) {
        #pragma unroll
        for (int d = 0; d < 2; d++) {
            const int io = s * 64 + d * 32;
            #pragma unroll
            for (int u = 0; u < 2; u++) {
                CP_ASYNC16(xdst[u] + (uint32_t)(s * 16384 + d * 8192), xsrc[u] + io);
                CP_ASYNC16(adst[u] + (uint32_t)(s * 16384 + d * 8192), asrc[u] + io);
            }
        }
        if (t < 32) CP_ASYNC16(esdst + (uint32_t)(s * 1024), essrc + s * 64);
        CP_COMMIT();
    }

    int buf = 0, wbuf = 2;
    for (int ch = 0; ch < 32; ++ch) {
        CP_WAIT1();
        __syncthreads();

        if (ch <= 29) {
            const int s = ch + 2;
            #pragma unroll
            for (int d = 0; d < 2; d++) {
                const int io = s * 64 + d * 32;
                #pragma unroll
                for (int u = 0; u < 2; u++) {
                    CP_ASYNC16(xdst[u] + (uint32_t)(wbuf * 16384 + d * 8192), xsrc[u] + io);
                    CP_ASYNC16(adst[u] + (uint32_t)(wbuf * 16384 + d * 8192), asrc[u] + io);
                }
            }
            if (t < 32) CP_ASYNC16(esdst + (uint32_t)(wbuf * 1024), essrc + s * 64);
            CP_COMMIT();
            wbuf = (wbuf == 2) ? 0 : wbuf + 1;
        } else {
            CP_COMMIT();
        }

        #pragma unroll
        for (int d = 0; d < 2; d++) {
            const uint32_t esb0 = sb + ES_OFFB + (uint32_t)(buf * 1024 + d * 512 + chead * 128);
            const uint32_t esb2 = esb0 + 256u;
            const uint32_t xtb  = sb + XT_OFFB + (uint32_t)(buf * 16384 + d * 8192 + chead * 4096);
            const uint32_t ahb  = sb + AH_OFFB + (uint32_t)(buf * 16384 + d * 8192);

            #pragma unroll
            for (int ks = 0; ks < 2; ks++) {
                const uint32_t eo = (uint32_t)(ks * 32 + tg * 4);
                uint32_t uesA = lds32u(esb0 + eo);
                uint32_t uesB = lds32u(esb0 + eo + 16u);
                uint32_t ue2A = lds32u(esb2 + eo);
                uint32_t ue2B = lds32u(esb2 + eo + 16u);
                const __half2 esA = *(__half2*)&uesA, esB = *(__half2*)&uesB;
                const __half2 e2A = *(__half2*)&ue2A, e2B = *(__half2*)&ue2B;

                uint32_t aT[4], bT[4];
                #pragma unroll
                for (int r = 0; r < 4; r++) {
                    const uint32_t rb  = ahb + (uint32_t)(rows[r] * 64);
                    const uint32_t sxr = (uint32_t)(((rows[r] >> 1) & 3) << 2);
                    uint32_t mA = lds32u(rb + ((((uint32_t)(ks * 8 + tg)) ^ sxr) << 2));
                    uint32_t mB = lds32u(rb + ((((uint32_t)(ks * 8 + tg + 4)) ^ sxr) << 2));
                    __half2 va = __hmax2(__hmul2(esA, edh[r]), __hmul2(e2A, ed2h[r]));
                    __half2 vb = __hmax2(__hmul2(esB, edh[r]), __hmul2(e2B, ed2h[r]));
                    aT[r] = (*(uint32_t*)&va) & mA;
                    bT[r] = (*(uint32_t*)&vb) & mB;
                }

                #pragma unroll
                for (int nt = 0; nt < 8; nt++) {
                    const int r = nt * 8 + g;
                    const uint32_t g16 = (uint32_t)(ks * 2 + (tg >> 1)) ^ (uint32_t)((r >> 1) & 3);
                    uint2 u = lds64u(xtb + (uint32_t)(r * 64) + g16 * 16u + (uint32_t)((tg & 1) * 8));
                    mma16(acc[0][nt], aT[0], aT[1], bT[0], bT[1], u.x, u.y);
                    mma16(acc[1][nt], aT[2], aT[3], bT[2], bT[3], u.x, u.y);
                }
                mma16(accl[0], aT[0], aT[1], bT[0], bT[1], ONES_H2, ONES_H2);
                mma16(accl[1], aT[2], aT[3], bT[2], bT[3], ONES_H2, ONES_H2);
            }
        }
        buf = (buf == 2) ? 0 : buf + 1;
    }

    // ---- epilogue: normalize, +bias, ELU, store
    const float* bp = bias + (size_t)(h0 + chead) * Cc;
    #pragma unroll
    for (int mt = 0; mt < 2; mt++) {
        const int r0 = ctw * 32 + mt * 16 + g;
        const int r1 = r0 + 8;
        const float inv0 = 1.f / accl[mt][0];
        const float inv1 = 1.f / accl[mt][2];
        float* o0 = out + (bn0 + j0 + r0) * HC + (size_t)(h0 + chead) * Cc;
        float* o1 = out + (bn0 + j0 + r1) * HC + (size_t)(h0 + chead) * Cc;
        #pragma unroll
        for (int nt = 0; nt < 8; nt++) {
            const int c = nt * 8 + tg * 2;
            const float b0v = bp[c], b1v = bp[c + 1];
            float w0 = acc[mt][nt][0] * inv0 + b0v;
            float w1 = acc[mt][nt][1] * inv0 + b1v;
            float w2 = acc[mt][nt][2] * inv1 + b0v;
            float w3 = acc[mt][nt][3] * inv1 + b1v;
            w0 = w0 > 0.f ? w0 : (fexp(w0) - 1.f);
            w1 = w1 > 0.f ? w1 : (fexp(w1) - 1.f);
            w2 = w2 > 0.f ? w2 : (fexp(w2) - 1.f);
            w3 = w3 > 0.f ? w3 : (fexp(w3) - 1.f);
            *(float2*)(o0 + c) = make_float2(w0, w1);
            *(float2*)(o1 + c) = make_float2(w2, w3);
        }
    }
}

// ---------------------------------------------------------------------------
extern "C" void kernel_launch(void* const* d_in, const int* in_sizes, int n_in,
                              void* d_out, int out_size)
{
    const float* feats   = (const float*)d_in[0];
    const int*   adj     = (const int*)  d_in[1];
    const float* W       = (const float*)d_in[2];
    const float* att_src = (const float*)d_in[3];
    const float* att_dst = (const float*)d_in[4];
    const float* bias    = (const float*)d_in[5];
    float*       out     = (float*)d_out;
    (void)in_sizes; (void)n_in; (void)out_size;

    static bool attr_set = false;
    if (!attr_set) {
        cudaFuncSetAttribute(gat_agg_mma,
                             cudaFuncAttributeMaxDynamicSharedMemorySize, AGG_SMEM);
        cudaFuncSetAttribute(gemm_proj_mma,
                             cudaFuncAttributeMaxDynamicSharedMemorySize, PROJ_SMEM);
        attr_set = true;
    }

    h16_feats<<<(Bz * Nn * Dd / 8) / 256, 256>>>(feats);
    h16_wt<<<dim3(Dd / 32, HC / 32), 256>>>(W);
    pack_adjH<<<dim3(Nn / 32, Nn / 32, Bz), 256>>>(adj);
    gemm_proj_mma<<<dim3((Bz * Nn) / 128, HC / 128), 256, PROJ_SMEM>>>(
        att_src, att_dst);
    gat_agg_mma<<<dim3(Nn / 128, Hh / 2, Bz), 256, AGG_SMEM>>>(bias, out);
}

// round 17
// speedup vs baseline: 1.4112x; 1.0586x over previous
#include <cuda_runtime.h>
#include <cuda_fp16.h>
#include <cstdint>
#include <math.h>

#define Bz 4
#define Nn 2048
#define Dd 512
#define Hh 8
#define Cc 64
#define HC 512

// ---------------- device scratch ----------------
__device__ __half g_Ah [(size_t)Bz * Nn * Dd];   // feats fp16, k-pair permuted per 16-group
__device__ __half g_WtH[(size_t)HC * Dd];        // W^T fp16 [n][k], k-pair permuted
__device__ __half g_XTh[(size_t)Bz * HC * Nn];   // x transposed fp16, i-pair permuted
__device__ __half g_EsH [(size_t)Bz * Hh * Nn];  // exp(s-4)  fp16 [b][h][n]
__device__ __half g_Es2H[(size_t)Bz * Hh * Nn];  // exp(.2s-4) fp16
__device__ float  g_EdT [(size_t)Bz * Hh * Nn];  // exp(d)   fp32
__device__ float  g_Ed2T[(size_t)Bz * Hh * Nn];  // exp(.2d) fp32
__device__ unsigned short g_adjH[(size_t)Bz * Nn * Nn]; // mask [b][j][i] 0xFFFF/0, diag folded

// ---------------- helpers ----------------
__device__ __forceinline__ uint32_t smem_u32(const void* p) {
    uint32_t a;
    asm("{ .reg .u64 t; cvta.to.shared.u64 t, %1; cvt.u32.u64 %0, t; }"
        : "=r"(a) : "l"(p));
    return a;
}
__device__ __forceinline__ uint2 lds64u(uint32_t a) {
    uint2 v;
    asm volatile("ld.shared.v2.u32 {%0,%1}, [%2];"
                 : "=r"(v.x), "=r"(v.y) : "r"(a));
    return v;
}
__device__ __forceinline__ float2 lds64f(uint32_t a) {
    float2 v;
    asm volatile("ld.shared.v2.f32 {%0,%1}, [%2];"
                 : "=f"(v.x), "=f"(v.y) : "r"(a));
    return v;
}
__device__ __forceinline__ uint32_t lds32u(uint32_t a) {
    uint32_t v;
    asm volatile("ld.shared.u32 %0, [%1];" : "=r"(v) : "r"(a));
    return v;
}
__device__ __forceinline__ void sts16(uint32_t a, uint16_t v) {
    asm volatile("st.shared.u16 [%0], %1;" :: "r"(a), "h"(v) : "memory");
}
__device__ __forceinline__ void sts64f(uint32_t a, float2 v) {
    asm volatile("st.shared.v2.f32 [%0], {%1,%2};"
                 :: "r"(a), "f"(v.x), "f"(v.y) : "memory");
}
__device__ __forceinline__ uint16_t f2h(float f) {
    __half h = __float2half_rn(f);
    return *(uint16_t*)&h;
}

#define CP_ASYNC16(dst, src) \
    asm volatile("cp.async.cg.shared.global [%0], [%1], 16;" \
                 :: "r"(dst), "l"(src) : "memory")
#define CP_COMMIT()  asm volatile("cp.async.commit_group;" ::: "memory")
#define CP_WAIT1()   asm volatile("cp.async.wait_group 1;" ::: "memory")
#define CP_WAIT2()   asm volatile("cp.async.wait_group 2;" ::: "memory")

// fp16 mma
__device__ __forceinline__ void mma16(float* d,
                                      uint32_t a0, uint32_t a1, uint32_t a2, uint32_t a3,
                                      uint32_t b0, uint32_t b1) {
    asm volatile(
        "mma.sync.aligned.m16n8k16.row.col.f32.f16.f16.f32 "
        "{%0,%1,%2,%3}, {%4,%5,%6,%7}, {%8,%9}, {%0,%1,%2,%3};"
        : "+f"(d[0]), "+f"(d[1]), "+f"(d[2]), "+f"(d[3])
        : "r"(a0), "r"(a1), "r"(a2), "r"(a3), "r"(b0), "r"(b1));
}
#define ONES_H2 0x3C003C00u

// ---------------- fast exp (FFMA-only) ----------------
__device__ __forceinline__ float fexp(float x) {
    const float LOG2E = 1.4426950408889634f;
    float t = x * LOG2E;
    float z = t + 12582912.0f;
    int   n = __float_as_int(z) - 0x4B400000;
    float r = z - 12582912.0f;
    float f = t - r;
    float u = f * 0.69314718056f;
    float p = 8.3333333e-3f;
    p = p * u + 4.1666667e-2f;
    p = p * u + 1.6666667e-1f;
    p = p * u + 0.5f;
    p = p * u + 1.0f;
    p = p * u + 1.0f;
    return p * __int_as_float((n + 127) << 23);
}

// ---------------------------------------------------------------------------
// Kernel 0a: feats fp32 -> fp16, k-pair permuted: one 16-k group per thread.
// src word w (halfs 2w,2w+1) -> dest word ((w&3)<<1)|(w>>2)
// ---------------------------------------------------------------------------
__global__ __launch_bounds__(256) void h16_feats(const float* __restrict__ A)
{
    const size_t i = (size_t)blockIdx.x * 256 + threadIdx.x;   // group index
    const float* src = A + i * 16;
    float4 v[4];
    #pragma unroll
    for (int p = 0; p < 4; p++) v[p] = ((const float4*)src)[p];
    const float* f = (const float*)v;
    uint32_t dw[8];
    #pragma unroll
    for (int w = 0; w < 8; w++) {
        __half2 h = __floats2half2_rn(f[2 * w], f[2 * w + 1]);
        dw[((w & 3) << 1) | (w >> 2)] = *(uint32_t*)&h;
    }
    uint4* o = (uint4*)(g_Ah + i * 16);
    o[0] = make_uint4(dw[0], dw[1], dw[2], dw[3]);
    o[1] = make_uint4(dw[4], dw[5], dw[6], dw[7]);
}

// ---------------------------------------------------------------------------
// Kernel 0b: W [k][n] fp32 -> Wt [n][k] fp16, k-pair permuted per 16-group
// ---------------------------------------------------------------------------
__global__ __launch_bounds__(256) void h16_wt(const float* __restrict__ Wm)
{
    __shared__ float ts[32][33];
    const int k0 = blockIdx.x << 5;
    const int n0 = blockIdx.y << 5;
    const int r  = threadIdx.x >> 5;
    const int cl = threadIdx.x & 31;
    #pragma unroll
    for (int rr = 0; rr < 32; rr += 8)
        ts[r + rr][cl] = Wm[(size_t)(k0 + r + rr) * HC + n0 + cl];
    __syncthreads();
    const int grp = cl >> 4, wg = (cl >> 1) & 7, hb = cl & 1;
    const int pos = grp * 16 + ((((wg & 3) << 1) | (wg >> 2)) << 1) + hb;
    #pragma unroll
    for (int rr = 0; rr < 32; rr += 8)
        g_WtH[(size_t)(n0 + r + rr) * Dd + k0 + pos] = __float2half_rn(ts[cl][r + rr]);
}

// ---------------------------------------------------------------------------
// Kernel 1: adjacency -> transposed fp16 AND-mask (diag folded) — unchanged
// ---------------------------------------------------------------------------
__global__ __launch_bounds__(256) void pack_adjH(const int* __restrict__ adj)
{
    __shared__ unsigned short ts[32][36];
    const int b  = blockIdx.z;
    const int i0 = blockIdx.y * 32;
    const int j0 = blockIdx.x * 32;
    const int t  = threadIdx.x;
    const int r  = t >> 3;
    const int c4 = t & 7;

    int4 v = *(const int4*)(adj + ((size_t)b * Nn + i0 + r) * Nn + j0 + c4 * 4);
    const int ii = i0 + r;
    ts[r][c4 * 4 + 0] = (v.x != 0 || ii == j0 + c4 * 4 + 0) ? 0xFFFFu : 0u;
    ts[r][c4 * 4 + 1] = (v.y != 0 || ii == j0 + c4 * 4 + 1) ? 0xFFFFu : 0u;
    ts[r][c4 * 4 + 2] = (v.z != 0 || ii == j0 + c4 * 4 + 2) ? 0xFFFFu : 0u;
    ts[r][c4 * 4 + 3] = (v.w != 0 || ii == j0 + c4 * 4 + 3) ? 0xFFFFu : 0u;
    __syncthreads();

    const int jr  = t >> 3;
    const int ic4 = t & 7;
    uint32_t lo = (uint32_t)ts[ic4 * 4 + 0][jr] | ((uint32_t)ts[ic4 * 4 + 1][jr] << 16);
    uint32_t hi = (uint32_t)ts[ic4 * 4 + 2][jr] | ((uint32_t)ts[ic4 * 4 + 3][jr] << 16);
    *(uint2*)(g_adjH + ((size_t)b * Nn + j0 + jr) * Nn + i0 + ic4 * 4) =
        make_uint2(lo, hi);
}

// ---------------------------------------------------------------------------
// Kernel 2: projection GEMM — fp16 m16n8k16, k-pair permuted operands:
// every fragment pair is ONE ld.shared.v2 (12 LDS.64/warp-iter, was 24 LDS.32).
// Fused epilogues unchanged: att dots -> exp tables; permuted fp16 transpose.
// ---------------------------------------------------------------------------
#define PA_OFF 0u          // 4 stages x 4096B (128 rows x 32B)
#define PB_OFF 16384u      // 4 stages x 4096B
#define RED_OFF 36864u     // epilogue A reduce region
#define PROJ_SMEM 46080u

__global__ void __launch_bounds__(256, 2) gemm_proj_mma(
    const float* __restrict__ att_src, const float* __restrict__ att_dst)
{
    extern __shared__ float sm[];
    const uint32_t sb = smem_u32(sm);

    const int t  = threadIdx.x;
    const int m0 = blockIdx.x * 128;
    const int n0 = blockIdx.y * 128;
    const int wid = t >> 5, lane = t & 31;
    const int wm = wid & 1, wn = wid >> 1;
    const int g = lane >> 2, tg = lane & 3;

    float acc[4][4][4];
    #pragma unroll
    for (int i = 0; i < 4; i++)
        #pragma unroll
        for (int j = 0; j < 4; j++)
            #pragma unroll
            for (int r = 0; r < 4; r++) acc[i][j][r] = 0.f;

    const int crow = t >> 1, cq = t & 1;
    const __half* aSrc = g_Ah  + (size_t)(m0 + crow) * Dd + cq * 8;
    const __half* bSrc = g_WtH + (size_t)(n0 + crow) * Dd + cq * 8;
    const uint32_t aDst = sb + PA_OFF + (uint32_t)(crow * 32 + cq * 16);
    const uint32_t bDst = sb + PB_OFF + (uint32_t)(crow * 32 + cq * 16);

    #pragma unroll
    for (int s = 0; s < 3; s++) {
        CP_ASYNC16(aDst + s * 4096u, aSrc + s * 16);
        CP_ASYNC16(bDst + s * 4096u, bSrc + s * 16);
        CP_COMMIT();
    }

    for (int kc = 0; kc < 32; ++kc) {
        const int buf = kc & 3;
        CP_WAIT2();
        __syncthreads();
        if (kc < 29) {
            const int s = (kc + 3) & 3, k0 = (kc + 3) * 16;
            CP_ASYNC16(aDst + s * 4096u, aSrc + k0);
            CP_ASYNC16(bDst + s * 4096u, bSrc + k0);
            CP_COMMIT();
        } else {
            CP_COMMIT();
        }

        const uint32_t Ab = sb + PA_OFF + buf * 4096u + (uint32_t)(wm * 64 * 32 + tg * 8);
        const uint32_t Bb = sb + PB_OFF + buf * 4096u + (uint32_t)(wn * 32 * 32 + tg * 8);

        uint2 alo[4], ahi[4];
        #pragma unroll
        for (int mt = 0; mt < 4; mt++) {
            const uint32_t base = Ab + (uint32_t)((mt * 16 + g) * 32);
            alo[mt] = lds64u(base);           // (a0, a2): row r, k and k+8
            ahi[mt] = lds64u(base + 256u);    // (a1, a3): row r+8
        }
        uint2 bf[4];
        #pragma unroll
        for (int nt = 0; nt < 4; nt++)
            bf[nt] = lds64u(Bb + (uint32_t)((nt * 8 + g) * 32));   // (b0, b1)
        #pragma unroll
        for (int mt = 0; mt < 4; mt++)
            #pragma unroll
            for (int nt = 0; nt < 4; nt++)
                mma16(acc[mt][nt], alo[mt].x, ahi[mt].x, alo[mt].y, ahi[mt].y,
                      bf[nt].x, bf[nt].y);
    }

    __syncthreads();   // staging dead; SMEM reusable

    // ---- epilogue A: per-row attention dots from registers
    {
        float s[4][2], dd[4][2];
        #pragma unroll
        for (int mt = 0; mt < 4; mt++) {
            s[mt][0] = s[mt][1] = 0.f;
            dd[mt][0] = dd[mt][1] = 0.f;
        }
        const int cbase = n0 + wn * 32 + tg * 2;
        #pragma unroll
        for (int nt = 0; nt < 4; nt++) {
            const float a0 = __ldg(att_src + cbase + nt * 8);
            const float a1 = __ldg(att_src + cbase + nt * 8 + 1);
            const float d0 = __ldg(att_dst + cbase + nt * 8);
            const float d1 = __ldg(att_dst + cbase + nt * 8 + 1);
            #pragma unroll
            for (int mt = 0; mt < 4; mt++) {
                s[mt][0]  += acc[mt][nt][0] * a0 + acc[mt][nt][1] * a1;
                s[mt][1]  += acc[mt][nt][2] * a0 + acc[mt][nt][3] * a1;
                dd[mt][0] += acc[mt][nt][0] * d0 + acc[mt][nt][1] * d1;
                dd[mt][1] += acc[mt][nt][2] * d0 + acc[mt][nt][3] * d1;
            }
        }
        #pragma unroll
        for (int o = 1; o < 4; o <<= 1) {
            #pragma unroll
            for (int mt = 0; mt < 4; mt++) {
                s[mt][0]  += __shfl_xor_sync(0xffffffffu, s[mt][0], o);
                s[mt][1]  += __shfl_xor_sync(0xffffffffu, s[mt][1], o);
                dd[mt][0] += __shfl_xor_sync(0xffffffffu, dd[mt][0], o);
                dd[mt][1] += __shfl_xor_sync(0xffffffffu, dd[mt][1], o);
            }
        }
        if (tg == 0) {
            const int hh = wn >> 1, half = wn & 1;
            #pragma unroll
            for (int mt = 0; mt < 4; mt++) {
                #pragma unroll
                for (int rh = 0; rh < 2; rh++) {
                    const int r = wm * 64 + mt * 16 + rh * 8 + g;
                    sts64f(sb + RED_OFF + (uint32_t)(((hh * 2 + half) * 128 + r) * 8),
                           make_float2(s[mt][rh], dd[mt][rh]));
                }
            }
        }
    }

    // ---- epilogue B stage: transpose acc -> fp16 staging
    #pragma unroll
    for (int mt = 0; mt < 4; mt++) {
        const int ml = wm * 64 + mt * 16 + g;
        #pragma unroll
        for (int nt = 0; nt < 4; nt++) {
            const int hcl = wn * 32 + nt * 8 + tg * 2;
            sts16(sb + (uint32_t)(hcl * 272 + ml * 2),             f2h(acc[mt][nt][0]));
            sts16(sb + (uint32_t)((hcl + 1) * 272 + ml * 2),       f2h(acc[mt][nt][1]));
            sts16(sb + (uint32_t)(hcl * 272 + (ml + 8) * 2),       f2h(acc[mt][nt][2]));
            sts16(sb + (uint32_t)((hcl + 1) * 272 + (ml + 8) * 2), f2h(acc[mt][nt][3]));
        }
    }
    __syncthreads();

    const int bb = m0 >> 11, mloc = m0 & 2047;

    // ---- epilogue A finish: reduce halves, exp, store tables
    {
        const int hh = t & 1, m = t >> 1;
        float2 pA = lds64f(sb + RED_OFF + (uint32_t)(((hh * 2 + 0) * 128 + m) * 8));
        float2 pB = lds64f(sb + RED_OFF + (uint32_t)(((hh * 2 + 1) * 128 + m) * 8));
        const float s = pA.x + pB.x;
        const float d = pA.y + pB.y;
        const int h = blockIdx.y * 2 + hh;
        const size_t o = ((size_t)bb * Hh + h) * Nn + mloc + m;
        g_EsH [o] = __float2half_rn(fexp(s - 4.0f));
        g_Es2H[o] = __float2half_rn(fexp(0.2f * s - 4.0f));
        g_EdT [o] = fexp(d);
        g_Ed2T[o] = fexp(0.2f * d);
    }

    // ---- epilogue B finish: permuted fp16 transpose out
    #pragma unroll 1
    for (int pass = 0; pass < 16; pass++) {
        const int row = pass * 8 + (t >> 5);
        const int ln  = t & 31;
        __half* orow = g_XTh + ((size_t)bb * HC + n0 + row) * Nn + mloc;
        #pragma unroll
        for (int k = 0; k < 2; k++) {
            const int wi = ln + k * 32;
            const int w16 = wi & 15, grp = wi >> 4;
            const int p16 = (w16 & 8) | ((w16 & 3) << 1) | ((w16 >> 2) & 1);
            uint32_t v = lds32u(sb + (uint32_t)(row * 272 + wi * 4));
            *(uint32_t*)(orow + (grp * 16 + p16) * 2) = v;
        }
    }
}

// ---------------------------------------------------------------------------
// Kernel 3: fused masked-softmax aggregation (unchanged — proven R14/15/16)
// ---------------------------------------------------------------------------
#define XT_OFFB  0u
#define AH_OFFB  49152u
#define ES_OFFB  98304u
#define AGG_SMEM 101376u

__global__ void __launch_bounds__(256, 2) gat_agg_mma(
    const float* __restrict__ bias, float* __restrict__ out)
{
    extern __shared__ float sm[];
    const uint32_t sb = smem_u32(sm);

    const int t  = threadIdx.x;
    const int b  = blockIdx.z;
    const int h0 = blockIdx.y * 2;
    const int j0 = blockIdx.x * 128;

    const int wid = t >> 5, lane = t & 31;
    const int chead = wid >> 2, ctw = wid & 3;
    const int g = lane >> 2, tg = lane & 3;

    const size_t bn0 = (size_t)b * Nn;
    const size_t edb = ((size_t)b * Hh + h0 + chead) * Nn + j0;

    int rows[4]; __half2 edh[4], ed2h[4];
    #pragma unroll
    for (int r = 0; r < 4; r++) {
        rows[r] = ctw * 32 + (r >> 1) * 16 + (r & 1) * 8 + g;
        edh[r]  = __half2half2(__float2half_rn(g_EdT [edb + rows[r]]));
        ed2h[r] = __half2half2(__float2half_rn(g_Ed2T[edb + rows[r]]));
    }

    float acc[2][8][4];
    #pragma unroll
    for (int m = 0; m < 2; m++)
        #pragma unroll
        for (int n = 0; n < 8; n++)
            #pragma unroll
            for (int r = 0; r < 4; r++) acc[m][n][r] = 0.f;
    float accl[2][4];
    #pragma unroll
    for (int m = 0; m < 2; m++)
        #pragma unroll
        for (int r = 0; r < 4; r++) accl[m][r] = 0.f;

    const __half* xsrc[2]; uint32_t xdst[2];
    const unsigned short* asrc[2]; uint32_t adst[2];
    #pragma unroll
    for (int u = 0; u < 2; u++) {
        int gid = u * 256 + t;
        int row = gid >> 2, q = gid & 3;
        int hh = row >> 6, c = row & 63;
        xsrc[u] = g_XTh + ((size_t)b * HC + (size_t)(h0 + hh) * Cc + c) * Nn + q * 8;
        xdst[u] = sb + XT_OFFB + (uint32_t)(row * 64 + ((q ^ ((row >> 1) & 3)) << 4));
        asrc[u] = g_adjH + (bn0 + j0 + row) * Nn + q * 8;
        adst[u] = sb + AH_OFFB + (uint32_t)(row * 64 + ((q ^ ((row >> 1) & 3)) << 4));
    }
    const __half* essrc = nullptr; uint32_t esdst = 0;
    if (t < 32) {
        int sub = t >> 4, tt = t & 15;
        int seg = tt >> 2, gi = tt & 3;
        int var = seg >> 1, hh = seg & 1;
        const __half* tbl = var ? g_Es2H : g_EsH;
        essrc = tbl + ((size_t)b * Hh + h0 + hh) * Nn + sub * 32 + gi * 8;
        esdst = sb + ES_OFFB + (uint32_t)(sub * 512 + var * 256 + hh * 128 + gi * 16);
    }

    #pragma unroll
    for (int s = 0; s < 2; s++) {
        #pragma unroll
        for (int d = 0; d < 2; d++) {
            const int io = s * 64 + d * 32;
            #pragma unroll
            for (int u = 0; u < 2; u++) {
                CP_ASYNC16(xdst[u] + (uint32_t)(s * 16384 + d * 8192), xsrc[u] + io);
                CP_ASYNC16(adst[u] + (uint32_t)(s * 16384 + d * 8192), asrc[u] + io);
            }
        }
        if (t < 32) CP_ASYNC16(esdst + (uint32_t)(s * 1024), essrc + s * 64);
        CP_COMMIT();
    }

    int buf = 0, wbuf = 2;
    for (int ch = 0; ch < 32; ++ch) {
        CP_WAIT1();
        __syncthreads();

        if (ch <= 29) {
            const int s = ch + 2;
            #pragma unroll
            for (int d = 0; d < 2; d++) {
                const int io = s * 64 + d * 32;
                #pragma unroll
                for (int u = 0; u < 2; u++) {
                    CP_ASYNC16(xdst[u] + (uint32_t)(wbuf * 16384 + d * 8192), xsrc[u] + io);
                    CP_ASYNC16(adst[u] + (uint32_t)(wbuf * 16384 + d * 8192), asrc[u] + io);
                }
            }
            if (t < 32) CP_ASYNC16(esdst + (uint32_t)(wbuf * 1024), essrc + s * 64);
            CP_COMMIT();
            wbuf = (wbuf == 2) ? 0 : wbuf + 1;
        } else {
            CP_COMMIT();
        }

        #pragma unroll
        for (int d = 0; d < 2; d++) {
            const uint32_t esb0 = sb + ES_OFFB + (uint32_t)(buf * 1024 + d * 512 + chead * 128);
            const uint32_t esb2 = esb0 + 256u;
            const uint32_t xtb  = sb + XT_OFFB + (uint32_t)(buf * 16384 + d * 8192 + chead * 4096);
            const uint32_t ahb  = sb + AH_OFFB + (uint32_t)(buf * 16384 + d * 8192);

            #pragma unroll
            for (int ks = 0; ks < 2; ks++) {
                const uint32_t eo = (uint32_t)(ks * 32 + tg * 4);
                uint32_t uesA = lds32u(esb0 + eo);
                uint32_t uesB = lds32u(esb0 + eo + 16u);
                uint32_t ue2A = lds32u(esb2 + eo);
                uint32_t ue2B = lds32u(esb2 + eo + 16u);
                const __half2 esA = *(__half2*)&uesA, esB = *(__half2*)&uesB;
                const __half2 e2A = *(__half2*)&ue2A, e2B = *(__half2*)&ue2B;

                uint32_t aT[4], bT[4];
                #pragma unroll
                for (int r = 0; r < 4; r++) {
                    const uint32_t rb  = ahb + (uint32_t)(rows[r] * 64);
                    const uint32_t sxr = (uint32_t)(((rows[r] >> 1) & 3) << 2);
                    uint32_t mA = lds32u(rb + ((((uint32_t)(ks * 8 + tg)) ^ sxr) << 2));
                    uint32_t mB = lds32u(rb + ((((uint32_t)(ks * 8 + tg + 4)) ^ sxr) << 2));
                    __half2 va = __hmax2(__hmul2(esA, edh[r]), __hmul2(e2A, ed2h[r]));
                    __half2 vb = __hmax2(__hmul2(esB, edh[r]), __hmul2(e2B, ed2h[r]));
                    aT[r] = (*(uint32_t*)&va) & mA;
                    bT[r] = (*(uint32_t*)&vb) & mB;
                }

                #pragma unroll
                for (int nt = 0; nt < 8; nt++) {
                    const int r = nt * 8 + g;
                    const uint32_t g16 = (uint32_t)(ks * 2 + (tg >> 1)) ^ (uint32_t)((r >> 1) & 3);
                    uint2 u = lds64u(xtb + (uint32_t)(r * 64) + g16 * 16u + (uint32_t)((tg & 1) * 8));
                    mma16(acc[0][nt], aT[0], aT[1], bT[0], bT[1], u.x, u.y);
                    mma16(acc[1][nt], aT[2], aT[3], bT[2], bT[3], u.x, u.y);
                }
                mma16(accl[0], aT[0], aT[1], bT[0], bT[1], ONES_H2, ONES_H2);
                mma16(accl[1], aT[2], aT[3], bT[2], bT[3], ONES_H2, ONES_H2);
            }
        }
        buf = (buf == 2) ? 0 : buf + 1;
    }

    // ---- epilogue: normalize, +bias, ELU, store
    const float* bp = bias + (size_t)(h0 + chead) * Cc;
    #pragma unroll
    for (int mt = 0; mt < 2; mt++) {
        const int r0 = ctw * 32 + mt * 16 + g;
        const int r1 = r0 + 8;
        const float inv0 = 1.f / accl[mt][0];
        const float inv1 = 1.f / accl[mt][2];
        float* o0 = out + (bn0 + j0 + r0) * HC + (size_t)(h0 + chead) * Cc;
        float* o1 = out + (bn0 + j0 + r1) * HC + (size_t)(h0 + chead) * Cc;
        #pragma unroll
        for (int nt = 0; nt < 8; nt++) {
            const int c = nt * 8 + tg * 2;
            const float b0v = bp[c], b1v = bp[c + 1];
            float w0 = acc[mt][nt][0] * inv0 + b0v;
            float w1 = acc[mt][nt][1] * inv0 + b1v;
            float w2 = acc[mt][nt][2] * inv1 + b0v;
            float w3 = acc[mt][nt][3] * inv1 + b1v;
            w0 = w0 > 0.f ? w0 : (fexp(w0) - 1.f);
            w1 = w1 > 0.f ? w1 : (fexp(w1) - 1.f);
            w2 = w2 > 0.f ? w2 : (fexp(w2) - 1.f);
            w3 = w3 > 0.f ? w3 : (fexp(w3) - 1.f);
            *(float2*)(o0 + c) = make_float2(w0, w1);
            *(float2*)(o1 + c) = make_float2(w2, w3);
        }
    }
}

// ---------------------------------------------------------------------------
extern "C" void kernel_launch(void* const* d_in, const int* in_sizes, int n_in,
                              void* d_out, int out_size)
{
    const float* feats   = (const float*)d_in[0];
    const int*   adj     = (const int*)  d_in[1];
    const float* W       = (const float*)d_in[2];
    const float* att_src = (const float*)d_in[3];
    const float* att_dst = (const float*)d_in[4];
    const float* bias    = (const float*)d_in[5];
    float*       out     = (float*)d_out;
    (void)in_sizes; (void)n_in; (void)out_size;

    static bool attr_set = false;
    if (!attr_set) {
        cudaFuncSetAttribute(gat_agg_mma,
                             cudaFuncAttributeMaxDynamicSharedMemorySize, AGG_SMEM);
        cudaFuncSetAttribute(gemm_proj_mma,
                             cudaFuncAttributeMaxDynamicSharedMemorySize, PROJ_SMEM);
        attr_set = true;
    }

    h16_feats<<<(Bz * Nn * Dd / 16) / 256, 256>>>(feats);
    h16_wt<<<dim3(Dd / 32, HC / 32), 256>>>(W);
    pack_adjH<<<dim3(Nn / 32, Nn / 32, Bz), 256>>>(adj);
    gemm_proj_mma<<<dim3((Bz * Nn) / 128, HC / 128), 256, PROJ_SMEM>>>(
        att_src, att_dst);
    gat_agg_mma<<<dim3(Nn / 128, Hh / 2, Bz), 256, AGG_SMEM>>>(bias, out);
}